// round 1
// baseline (speedup 1.0000x reference)
#include <cuda_runtime.h>
#include <math.h>

// Problem constants
#define Bn   8
#define Ln   256
#define Dn   1024
#define An   64
#define Vn   128
#define En   256
#define Gn   2048
#define Wn   255
#define DP1  1025          // D + 1 (biaffine augmented dim)
#define NEGV (-1000.0f)

// ---------------- scratch (device globals; no allocation allowed) ----------------
__device__ float g_T[Bn * Ln * DP1];        // xb @ W_biaffine   [2048, 1025]  (8.4 MB)
__device__ float g_gold[Bn * An * 2 * Dn];  // gold_repr         [512, 2048]   (4 MB)
__device__ float g_h1[Bn * An * En];        // pre-LN hidden     [512, 256]
__device__ float g_h[Bn * An * En];         // relu(LN(h1))      [512, 256]
__device__ float g_h2[Bn * An * En];        // second projection [512, 256]
__device__ float g_logits[Bn * An * Vn];    // label logits      [512, 128]
__device__ float g_span_part[136];          // 128 span-tile partials + 8 gold partials
__device__ float g_span_cnt[128];           // span mask counts per tile
__device__ float g_ce_part[Bn * An];        // per-row CE (masked)

// =====================================================================
// GEMM1 (NN): g_T[m][n] = sum_k reprs[m][k] * W[k][n] + W[1024][n]
// M=2048, N=1025, K=1024. 64x64 tiles, 256 threads, 4x4 per thread.
// =====================================================================
__global__ __launch_bounds__(256) void k_gemm1(const float* __restrict__ A,
                                               const float* __restrict__ Wb) {
    __shared__ __align__(16) float As[16][68];
    __shared__ __align__(16) float Bs[16][68];
    int tid = threadIdx.x, tx = tid & 15, ty = tid >> 4;
    int n0 = blockIdx.x * 64, m0 = blockIdx.y * 64;
    float acc[4][4] = {};

    for (int k0 = 0; k0 < 1024; k0 += 16) {
        #pragma unroll
        for (int i = 0; i < 4; i++) {
            int lin = tid + 256 * i;
            int r = lin >> 4, kk = lin & 15;
            As[kk][r] = A[(m0 + r) * 1024 + k0 + kk];
        }
        #pragma unroll
        for (int i = 0; i < 4; i++) {
            int lin = tid + 256 * i;
            int c = lin & 63, kk = lin >> 6;
            int col = n0 + c;
            Bs[kk][c] = (col < DP1) ? Wb[(k0 + kk) * DP1 + col] : 0.f;
        }
        __syncthreads();
        #pragma unroll
        for (int kk = 0; kk < 16; kk++) {
            float4 a4 = *reinterpret_cast<const float4*>(&As[kk][ty * 4]);
            float4 b4 = *reinterpret_cast<const float4*>(&Bs[kk][tx * 4]);
            float av[4] = {a4.x, a4.y, a4.z, a4.w};
            float bv[4] = {b4.x, b4.y, b4.z, b4.w};
            #pragma unroll
            for (int i = 0; i < 4; i++)
                #pragma unroll
                for (int j = 0; j < 4; j++) acc[i][j] += av[i] * bv[j];
        }
        __syncthreads();
    }
    #pragma unroll
    for (int i = 0; i < 4; i++) {
        int m = m0 + ty * 4 + i;
        #pragma unroll
        for (int j = 0; j < 4; j++) {
            int col = n0 + tx * 4 + j;
            if (col < DP1) g_T[m * DP1 + col] = acc[i][j] + Wb[1024 * DP1 + col];
        }
    }
}

// =====================================================================
// Span scores (NT, fused): s[b,x,y] = T[b,x,:1024]·reprs[b,y,:] + T[b,x,1024]
// Epilogue: masked softplus sum + mask count, per-tile partial.
// Grid: (4 y-tiles, 4 x-tiles, 8 batches), 256 threads.
// =====================================================================
__global__ __launch_bounds__(256) void k_span(const float* __restrict__ reprs,
                                              const int* __restrict__ seq_len) {
    __shared__ __align__(16) float As[16][68];
    __shared__ __align__(16) float Bs[16][68];
    __shared__ float red[256];
    int tid = threadIdx.x, tx = tid & 15, ty = tid >> 4;
    int b = blockIdx.z;
    int x0 = blockIdx.y * 64, y0 = blockIdx.x * 64;
    int slot = (b * 4 + blockIdx.y) * 4 + blockIdx.x;
    int sl = seq_len[b];

    // dead tile: entirely below/on diagonal, or entirely beyond seq_len
    if (y0 + 63 <= x0 || y0 > sl) {
        if (tid == 0) { g_span_part[slot] = 0.f; g_span_cnt[slot] = 0.f; }
        return;
    }

    const float* Arow = g_T + (b * Ln + x0) * DP1;
    const float* Brow = reprs + (b * Ln + y0) * Dn;
    float acc[4][4] = {};

    for (int k0 = 0; k0 < Dn; k0 += 16) {
        #pragma unroll
        for (int i = 0; i < 4; i++) {
            int lin = tid + 256 * i;
            int r = lin >> 4, kk = lin & 15;
            As[kk][r] = Arow[r * DP1 + k0 + kk];
            Bs[kk][r] = Brow[r * Dn + k0 + kk];
        }
        __syncthreads();
        #pragma unroll
        for (int kk = 0; kk < 16; kk++) {
            float4 a4 = *reinterpret_cast<const float4*>(&As[kk][ty * 4]);
            float4 b4 = *reinterpret_cast<const float4*>(&Bs[kk][tx * 4]);
            float av[4] = {a4.x, a4.y, a4.z, a4.w};
            float bv[4] = {b4.x, b4.y, b4.z, b4.w};
            #pragma unroll
            for (int i = 0; i < 4; i++)
                #pragma unroll
                for (int j = 0; j < 4; j++) acc[i][j] += av[i] * bv[j];
        }
        __syncthreads();
    }

    float lsum = 0.f, lcnt = 0.f;
    #pragma unroll
    for (int i = 0; i < 4; i++) {
        int x = x0 + ty * 4 + i;
        float tb = Arow[(ty * 4 + i) * DP1 + 1024];  // bias column (xb[y][1024]=1)
        #pragma unroll
        for (int j = 0; j < 4; j++) {
            int y = y0 + tx * 4 + j;
            if (y > x && y <= sl) {
                float s = acc[i][j] + tb;
                lsum += fmaxf(s, 0.f) + log1pf(expf(-fabsf(s)));  // softplus
                lcnt += 1.f;
            }
        }
    }
    red[tid] = lsum; __syncthreads();
    for (int s = 128; s > 0; s >>= 1) { if (tid < s) red[tid] += red[tid + s]; __syncthreads(); }
    float tot = red[0]; __syncthreads();
    red[tid] = lcnt; __syncthreads();
    for (int s = 128; s > 0; s >>= 1) { if (tid < s) red[tid] += red[tid + s]; __syncthreads(); }
    if (tid == 0) { g_span_part[slot] = tot; g_span_cnt[slot] = red[0]; }
}

// =====================================================================
// Gold spans: subtract s at deduped, in-mask gold positions.
// =====================================================================
__global__ __launch_bounds__(256) void k_gold(const float* __restrict__ reprs,
                                              const int* __restrict__ gold,
                                              const int* __restrict__ seq_len) {
    __shared__ float red[256];
    int tid = threadIdx.x;
    int g = blockIdx.x * 256 + tid;
    float val = 0.f;
    if (g < Gn) {
        int gb = gold[3 * g], gl = gold[3 * g + 1], gr = gold[3 * g + 2];
        if (gr > gl && gr <= seq_len[gb]) {
            bool first = true;   // reference uses .set(1.0): duplicates count once
            for (int p = 0; p < g; p++) {
                if (gold[3 * p] == gb && gold[3 * p + 1] == gl && gold[3 * p + 2] == gr) {
                    first = false; break;
                }
            }
            if (first) {
                const float* tr = g_T + (gb * Ln + gl) * DP1;
                const float* rr = reprs + (gb * Ln + gr) * Dn;
                float s = tr[1024];
                #pragma unroll 8
                for (int j = 0; j < Dn; j++) s += tr[j] * rr[j];
                val = -s;
            }
        }
    }
    red[tid] = val; __syncthreads();
    for (int s = 128; s > 0; s >>= 1) { if (tid < s) red[tid] += red[tid + s]; __syncthreads(); }
    if (tid == 0) g_span_part[128 + blockIdx.x] = red[0];
}

// =====================================================================
// gold_repr = concat(end - start, maxpool(word_repr[start:end]))  [512, 2048]
// =====================================================================
__global__ __launch_bounds__(256) void k_gold_repr(const float* __restrict__ reprs,
                                                   const float* __restrict__ word_repr,
                                                   const int* __restrict__ span_start,
                                                   const int* __restrict__ span_end) {
    int row = blockIdx.x, tid = threadIdx.x;
    int b = row >> 6;
    int s = span_start[row], e = span_end[row];
    const float* rs = reprs + (b * Ln + s) * Dn;
    const float* re = reprs + (b * Ln + e) * Dn;
    float* out = g_gold + row * 2 * Dn;
    #pragma unroll
    for (int i = 0; i < 4; i++) {
        int d = tid + 256 * i;
        out[d] = re[d] - rs[d];
    }
    float m0 = NEGV, m1 = NEGV, m2 = NEGV, m3 = NEGV;
    const float* wb = word_repr + (size_t)b * Wn * Dn;
    int ee = min(e, Wn);
    for (int w = s; w < ee; w++) {
        const float* wr = wb + w * Dn;
        m0 = fmaxf(m0, wr[tid]);
        m1 = fmaxf(m1, wr[tid + 256]);
        m2 = fmaxf(m2, wr[tid + 512]);
        m3 = fmaxf(m3, wr[tid + 768]);
    }
    out[Dn + tid]       = m0;
    out[Dn + tid + 256] = m1;
    out[Dn + tid + 512] = m2;
    out[Dn + tid + 768] = m3;
}

// =====================================================================
// Generic NT GEMM body: C[m][n] = sum_k A[m][k]*B[n][k] + bias[n]
// 64x64 tiles, 256 threads, 4x4 per thread. M,N,K all multiples of 64/16.
// =====================================================================
__device__ __forceinline__ void gemm_nt_body(const float* __restrict__ A,
                                             const float* __restrict__ Bm,
                                             const float* __restrict__ bias,
                                             float* __restrict__ C,
                                             int Kk, int lda, int ldb, int ldc) {
    __shared__ __align__(16) float As[16][68];
    __shared__ __align__(16) float Bs[16][68];
    int tid = threadIdx.x, tx = tid & 15, ty = tid >> 4;
    int n0 = blockIdx.x * 64, m0 = blockIdx.y * 64;
    float acc[4][4] = {};

    for (int k0 = 0; k0 < Kk; k0 += 16) {
        #pragma unroll
        for (int i = 0; i < 4; i++) {
            int lin = tid + 256 * i;
            int r = lin >> 4, kk = lin & 15;
            As[kk][r] = A[(m0 + r) * lda + k0 + kk];
            Bs[kk][r] = Bm[(n0 + r) * ldb + k0 + kk];
        }
        __syncthreads();
        #pragma unroll
        for (int kk = 0; kk < 16; kk++) {
            float4 a4 = *reinterpret_cast<const float4*>(&As[kk][ty * 4]);
            float4 b4 = *reinterpret_cast<const float4*>(&Bs[kk][tx * 4]);
            float av[4] = {a4.x, a4.y, a4.z, a4.w};
            float bv[4] = {b4.x, b4.y, b4.z, b4.w};
            #pragma unroll
            for (int i = 0; i < 4; i++)
                #pragma unroll
                for (int j = 0; j < 4; j++) acc[i][j] += av[i] * bv[j];
        }
        __syncthreads();
    }
    #pragma unroll
    for (int i = 0; i < 4; i++) {
        int m = m0 + ty * 4 + i;
        #pragma unroll
        for (int j = 0; j < 4; j++) {
            int col = n0 + tx * 4 + j;
            float bv = bias ? bias[col] : 0.f;
            C[m * ldc + col] = acc[i][j] + bv;
        }
    }
}

__global__ __launch_bounds__(256) void k_h1(const float* __restrict__ Wp1,
                                            const float* __restrict__ bp1) {
    gemm_nt_body(g_gold, Wp1, bp1, g_h1, 2 * Dn, 2 * Dn, 2 * Dn, En);
}
__global__ __launch_bounds__(256) void k_h2(const float* __restrict__ Wp2,
                                            const float* __restrict__ bp2) {
    gemm_nt_body(g_h, Wp2, bp2, g_h2, En, En, En, En);
}
__global__ __launch_bounds__(256) void k_logits(const float* __restrict__ lab) {
    gemm_nt_body(g_h2, lab, nullptr, g_logits, En, En, En, Vn);
}

// =====================================================================
// relu(LayerNorm(h1)) per row
// =====================================================================
__global__ __launch_bounds__(256) void k_ln(const float* __restrict__ gamma,
                                            const float* __restrict__ beta) {
    __shared__ float red[256];
    int row = blockIdx.x, tid = threadIdx.x;
    float x = g_h1[row * En + tid];
    red[tid] = x; __syncthreads();
    for (int s = 128; s > 0; s >>= 1) { if (tid < s) red[tid] += red[tid + s]; __syncthreads(); }
    float mean = red[0] * (1.0f / En); __syncthreads();
    float d = x - mean;
    red[tid] = d * d; __syncthreads();
    for (int s = 128; s > 0; s >>= 1) { if (tid < s) red[tid] += red[tid + s]; __syncthreads(); }
    float var = red[0] * (1.0f / En);
    float y = d * rsqrtf(var + 1e-5f) * gamma[tid] + beta[tid];
    g_h[row * En + tid] = fmaxf(y, 0.f);
}

// =====================================================================
// Per-row log-softmax + CE (masked by action_len)
// =====================================================================
__global__ __launch_bounds__(128) void k_ce(const int* __restrict__ chart,
                                            const int* __restrict__ action_len) {
    __shared__ float red[128];
    int row = blockIdx.x, tid = threadIdx.x;
    int b = row >> 6, a = row & 63;
    float l = g_logits[row * Vn + tid];
    red[tid] = l; __syncthreads();
    for (int s = 64; s > 0; s >>= 1) { if (tid < s) red[tid] = fmaxf(red[tid], red[tid + s]); __syncthreads(); }
    float mx = red[0]; __syncthreads();
    red[tid] = expf(l - mx); __syncthreads();
    for (int s = 64; s > 0; s >>= 1) { if (tid < s) red[tid] += red[tid + s]; __syncthreads(); }
    if (tid == 0) {
        float lse = logf(red[0]);
        int c = chart[row];
        float ce = -(g_logits[row * Vn + c] - mx - lse);
        g_ce_part[row] = (a < action_len[b]) ? ce : 0.f;
    }
}

// =====================================================================
// Final deterministic reduction: out = span_sum/span_cnt + ce_sum/label_cnt
// =====================================================================
__global__ __launch_bounds__(512) void k_final(const int* __restrict__ action_len,
                                               float* __restrict__ out) {
    __shared__ float red[512];
    int tid = threadIdx.x;
    float v = 0.f;
    for (int i = tid; i < 136; i += 512) v += g_span_part[i];
    red[tid] = v; __syncthreads();
    for (int s = 256; s > 0; s >>= 1) { if (tid < s) red[tid] += red[tid + s]; __syncthreads(); }
    float span_sum = red[0]; __syncthreads();

    v = 0.f;
    for (int i = tid; i < 128; i += 512) v += g_span_cnt[i];
    red[tid] = v; __syncthreads();
    for (int s = 256; s > 0; s >>= 1) { if (tid < s) red[tid] += red[tid + s]; __syncthreads(); }
    float span_cnt = red[0]; __syncthreads();

    red[tid] = g_ce_part[tid]; __syncthreads();
    for (int s = 256; s > 0; s >>= 1) { if (tid < s) red[tid] += red[tid + s]; __syncthreads(); }
    float ce_sum = red[0];

    if (tid == 0) {
        int lc = 0;
        for (int b = 0; b < Bn; b++) lc += action_len[b];
        out[0] = span_sum / span_cnt + ce_sum / (float)lc;
    }
}

// =====================================================================
// Launch
// =====================================================================
extern "C" void kernel_launch(void* const* d_in, const int* in_sizes, int n_in,
                              void* d_out, int out_size) {
    const float* reprs      = (const float*)d_in[0];
    const float* word_repr  = (const float*)d_in[1];
    const int*   seq_len    = (const int*)d_in[2];
    const int*   gold_span  = (const int*)d_in[3];
    const int*   span_start = (const int*)d_in[4];
    const int*   span_end   = (const int*)d_in[5];
    const int*   chart      = (const int*)d_in[6];
    const int*   action_len = (const int*)d_in[7];
    const float* Wb         = (const float*)d_in[8];
    const float* Wp1        = (const float*)d_in[9];
    const float* bp1        = (const float*)d_in[10];
    const float* gamma      = (const float*)d_in[11];
    const float* beta       = (const float*)d_in[12];
    const float* Wp2        = (const float*)d_in[13];
    const float* bp2        = (const float*)d_in[14];
    const float* lab        = (const float*)d_in[15];
    float* out = (float*)d_out;

    // Biaffine path
    k_gemm1<<<dim3(17, 32), 256>>>(reprs, Wb);               // T = xb @ W (+bias row)
    k_span<<<dim3(4, 4, 8), 256>>>(reprs, seq_len);          // masked softplus sum + count
    k_gold<<<8, 256>>>(reprs, gold_span, seq_len);           // -sum s at gold (deduped)

    // Label path
    k_gold_repr<<<Bn * An, 256>>>(reprs, word_repr, span_start, span_end);
    k_h1<<<dim3(4, 8), 256>>>(Wp1, bp1);                     // [512,2048]@[256,2048]^T
    k_ln<<<Bn * An, 256>>>(gamma, beta);                     // relu(LN)
    k_h2<<<dim3(4, 8), 256>>>(Wp2, bp2);                     // [512,256]@[256,256]^T
    k_logits<<<dim3(2, 8), 256>>>(lab);                      // [512,256]@[128,256]^T
    k_ce<<<Bn * An, 128>>>(chart, action_len);               // masked CE per row

    k_final<<<1, 512>>>(action_len, out);
}

// round 2
// speedup vs baseline: 3.7917x; 3.7917x over previous
#include <cuda_runtime.h>
#include <math.h>

// Problem constants
#define Bn   8
#define Ln   256
#define Dn   1024
#define An   64
#define Vn   128
#define En   256
#define Gn   2048
#define Wn   255
#define LDT  1028          // padded row stride for T (1025 cols, pad to %4==0)
#define NEGV (-1000.0f)

// ---------------- scratch (device globals) ----------------
__device__ float g_T[Bn * Ln * LDT];          // xb @ W_biaffine, padded  (~8.4 MB)
__device__ float g_sp[4 * Bn * Ln * Ln];      // split-K partials of s_span (8 MB)
__device__ float g_gold[Bn * An * 2 * Dn];    // gold_repr [512, 2048]
__device__ float g_h1p[16 * 512 * 256];       // split-K partials of h1 (8 MB)
__device__ float g_h[512 * 256];              // relu(LN(h1))
__device__ float g_span_sum[32];
__device__ float g_span_cnt2[32];
__device__ float g_gold_part[256];
__device__ float g_ce_part[512];

// =====================================================================
// 128x128 tile GEMM body. 256 threads, 8x8 per thread (2x2 of 4x4).
// A row-major [m][k]. B either NN ([k][n]) or NT ([n][k]).
// Per k-step: 4 conflict-free LDS.128 per 64 FFMA -> FFMA-bound.
// =====================================================================
template<bool BT>
__device__ __forceinline__ void gemm128_body(
    const float* __restrict__ A, const float* __restrict__ B,
    float* __restrict__ C,
    int lda, int ldb, int ldc,
    int m0, int n0, int k_begin, int k_end,
    const float* __restrict__ bias)
{
    __shared__ float As[8][132];
    __shared__ float Bs[8][132];
    int tid = threadIdx.x;
    int tx = tid & 15, ty = tid >> 4;
    float acc[2][2][4][4];
    #pragma unroll
    for (int a = 0; a < 2; a++)
        #pragma unroll
        for (int b = 0; b < 2; b++)
            #pragma unroll
            for (int i = 0; i < 4; i++)
                #pragma unroll
                for (int j = 0; j < 4; j++) acc[a][b][i][j] = 0.f;

    const float* Abase = A + (size_t)m0 * lda;

    for (int kc = k_begin; kc < k_end; kc += 8) {
        // A tile: 128 rows x 8 k, float4 per thread, transpose into As[k][m]
        {
            int r = tid >> 1, kq = (tid & 1) * 4;
            float4 v = *reinterpret_cast<const float4*>(Abase + (size_t)r * lda + kc + kq);
            As[kq + 0][r] = v.x; As[kq + 1][r] = v.y;
            As[kq + 2][r] = v.z; As[kq + 3][r] = v.w;
        }
        if (BT) {
            int r = tid >> 1, kq = (tid & 1) * 4;
            float4 v = *reinterpret_cast<const float4*>(B + (size_t)(n0 + r) * ldb + kc + kq);
            Bs[kq + 0][r] = v.x; Bs[kq + 1][r] = v.y;
            Bs[kq + 2][r] = v.z; Bs[kq + 3][r] = v.w;
        } else {
            int kr = tid >> 5, nq = tid & 31;   // scalar coalesced (ldb may be odd)
            #pragma unroll
            for (int j = 0; j < 4; j++)
                Bs[kr][nq + 32 * j] = B[(size_t)(kc + kr) * ldb + n0 + nq + 32 * j];
        }
        __syncthreads();
        #pragma unroll
        for (int kk = 0; kk < 8; kk++) {
            float4 a0v = *reinterpret_cast<const float4*>(&As[kk][ty * 4]);
            float4 a1v = *reinterpret_cast<const float4*>(&As[kk][64 + ty * 4]);
            float4 b0v = *reinterpret_cast<const float4*>(&Bs[kk][tx * 4]);
            float4 b1v = *reinterpret_cast<const float4*>(&Bs[kk][64 + tx * 4]);
            const float* a0 = &a0v.x; const float* a1 = &a1v.x;
            const float* b0 = &b0v.x; const float* b1 = &b1v.x;
            #pragma unroll
            for (int i = 0; i < 4; i++)
                #pragma unroll
                for (int j = 0; j < 4; j++) {
                    acc[0][0][i][j] += a0[i] * b0[j];
                    acc[0][1][i][j] += a0[i] * b1[j];
                    acc[1][0][i][j] += a1[i] * b0[j];
                    acc[1][1][i][j] += a1[i] * b1[j];
                }
        }
        __syncthreads();
    }
    // epilogue (ldc is %4==0 for all call sites -> float4 stores)
    #pragma unroll
    for (int ii = 0; ii < 2; ii++)
        #pragma unroll
        for (int i = 0; i < 4; i++) {
            int m = m0 + ii * 64 + ty * 4 + i;
            #pragma unroll
            for (int jj = 0; jj < 2; jj++) {
                int n = n0 + jj * 64 + tx * 4;
                float4 v;
                v.x = acc[ii][jj][i][0]; v.y = acc[ii][jj][i][1];
                v.z = acc[ii][jj][i][2]; v.w = acc[ii][jj][i][3];
                if (bias) { v.x += bias[n]; v.y += bias[n + 1]; v.z += bias[n + 2]; v.w += bias[n + 3]; }
                *reinterpret_cast<float4*>(C + (size_t)m * ldc + n) = v;
            }
        }
}

// ---- GEMM1 (NN): T[m][n] = reprs @ W + W[1024][n], main 1024 cols ----
__global__ __launch_bounds__(256) void k_gemm1(const float* __restrict__ A,
                                               const float* __restrict__ Wb) {
    gemm128_body<false>(A, Wb, g_T, 1024, 1025, LDT,
                        blockIdx.y * 128, blockIdx.x * 128, 0, 1024,
                        Wb + 1024 * 1025);
}

// ---- T bias column (n = 1024) ----
__global__ __launch_bounds__(256) void k_bias_col(const float* __restrict__ A,
                                                  const float* __restrict__ Wb) {
    __shared__ float wcol[1024];
    for (int i = threadIdx.x; i < 1024; i += 256) wcol[i] = Wb[i * 1025 + 1024];
    __syncthreads();
    int wid = threadIdx.x >> 5, lane = threadIdx.x & 31;
    float wbias = Wb[1024 * 1025 + 1024];
    #pragma unroll
    for (int rr = 0; rr < 4; rr++) {
        int row = blockIdx.x * 32 + wid * 4 + rr;
        const float* ar = A + (size_t)row * 1024;
        float s = 0.f;
        for (int j = lane * 4; j < 1024; j += 128) {
            float4 a = *reinterpret_cast<const float4*>(ar + j);
            s += a.x * wcol[j] + a.y * wcol[j + 1] + a.z * wcol[j + 2] + a.w * wcol[j + 3];
        }
        #pragma unroll
        for (int o = 16; o; o >>= 1) s += __shfl_xor_sync(0xffffffff, s, o);
        if (lane == 0) g_T[(size_t)row * LDT + 1024] = s + wbias;
    }
}

// ---- span GEMM (NT, split-K=4): partial s_span tiles ----
__global__ __launch_bounds__(256) void k_span_g(const float* __restrict__ reprs,
                                                const int* __restrict__ seq_len) {
    int bz = blockIdx.z;
    int ks = bz & 3, b = bz >> 2;
    int y0 = blockIdx.x * 128, x0 = blockIdx.y * 128;
    if (y0 + 127 <= x0) return;            // fully at/below diagonal
    if (y0 > seq_len[b]) return;           // fully beyond length
    gemm128_body<true>(g_T + (size_t)b * Ln * LDT,
                       reprs + (size_t)b * Ln * Dn,
                       g_sp + (size_t)(ks * Bn + b) * Ln * Ln,
                       LDT, Dn, Ln, x0, y0, ks * 256, ks * 256 + 256, nullptr);
}

// ---- span epilogue: sum split-K + bias, masked softplus sum + count ----
__global__ __launch_bounds__(256) void k_span_epi(const int* __restrict__ seq_len) {
    __shared__ float red[256];
    int b = blockIdx.x >> 2, xc = blockIdx.x & 3;
    int sl = seq_len[b];
    int tid = threadIdx.x;
    float lsum = 0.f, lcnt = 0.f;
    for (int xr = 0; xr < 64; xr++) {
        int x = xc * 64 + xr;
        int y = tid;
        if (y > x && y <= sl) {
            float tb = g_T[((size_t)b * Ln + x) * LDT + 1024];
            size_t base = ((size_t)b * Ln + x) * Ln + y;
            float s = g_sp[base]
                    + g_sp[(size_t)1 * Bn * Ln * Ln + base]
                    + g_sp[(size_t)2 * Bn * Ln * Ln + base]
                    + g_sp[(size_t)3 * Bn * Ln * Ln + base] + tb;
            lsum += fmaxf(s, 0.f) + log1pf(expf(-fabsf(s)));
            lcnt += 1.f;
        }
    }
    red[tid] = lsum; __syncthreads();
    for (int s = 128; s > 0; s >>= 1) { if (tid < s) red[tid] += red[tid + s]; __syncthreads(); }
    float tot = red[0]; __syncthreads();
    red[tid] = lcnt; __syncthreads();
    for (int s = 128; s > 0; s >>= 1) { if (tid < s) red[tid] += red[tid + s]; __syncthreads(); }
    if (tid == 0) { g_span_sum[blockIdx.x] = tot; g_span_cnt2[blockIdx.x] = red[0]; }
}

// ---- gold spans: warp per span, lane-parallel dedup, -sum s[gold] ----
__global__ __launch_bounds__(256) void k_gold(const float* __restrict__ reprs,
                                              const int* __restrict__ gold,
                                              const int* __restrict__ seq_len) {
    __shared__ float wsum[8];
    int wid = threadIdx.x >> 5, lane = threadIdx.x & 31;
    int g = blockIdx.x * 8 + wid;
    float val = 0.f;
    int gb = gold[3 * g], gl = gold[3 * g + 1], gr = gold[3 * g + 2];
    if (gr > gl && gr <= seq_len[gb]) {
        int key = (gb << 16) | (gl << 8) | gr;
        bool dup = false;
        for (int p = lane; p < g; p += 32) {
            int k2 = (gold[3 * p] << 16) | (gold[3 * p + 1] << 8) | gold[3 * p + 2];
            if (k2 == key) dup = true;
        }
        dup = __any_sync(0xffffffff, dup);
        if (!dup) {
            const float* tr = g_T + ((size_t)gb * Ln + gl) * LDT;
            const float* rr = reprs + ((size_t)gb * Ln + gr) * Dn;
            float s = 0.f;
            for (int j = lane * 4; j < 1024; j += 128) {
                float4 t = *reinterpret_cast<const float4*>(tr + j);
                float4 r = *reinterpret_cast<const float4*>(rr + j);
                s += t.x * r.x + t.y * r.y + t.z * r.z + t.w * r.w;
            }
            #pragma unroll
            for (int o = 16; o; o >>= 1) s += __shfl_xor_sync(0xffffffff, s, o);
            if (lane == 0) val = -(s + tr[1024]);
        }
    }
    if (lane == 0) wsum[wid] = val;
    __syncthreads();
    if (threadIdx.x == 0) {
        float t = 0.f;
        #pragma unroll
        for (int i = 0; i < 8; i++) t += wsum[i];
        g_gold_part[blockIdx.x] = t;
    }
}

// ---- gold_repr = concat(end-start, maxpool word_repr[start:end)) ----
__global__ __launch_bounds__(256) void k_gold_repr(const float* __restrict__ reprs,
                                                   const float* __restrict__ word_repr,
                                                   const int* __restrict__ span_start,
                                                   const int* __restrict__ span_end) {
    int row = blockIdx.x, tid = threadIdx.x;
    int b = row >> 6;
    int s = span_start[row], e = span_end[row];
    const float4* rs = reinterpret_cast<const float4*>(reprs + ((size_t)b * Ln + s) * Dn);
    const float4* re = reinterpret_cast<const float4*>(reprs + ((size_t)b * Ln + e) * Dn);
    float4* out = reinterpret_cast<float4*>(g_gold + (size_t)row * 2 * Dn);
    float4 a = re[tid], c = rs[tid];
    float4 d; d.x = a.x - c.x; d.y = a.y - c.y; d.z = a.z - c.z; d.w = a.w - c.w;
    out[tid] = d;
    float4 m; m.x = m.y = m.z = m.w = NEGV;
    const float4* wb = reinterpret_cast<const float4*>(word_repr + (size_t)b * Wn * Dn);
    int ee = min(e, Wn);
    for (int w = s; w < ee; w++) {
        float4 v = wb[(size_t)w * 256 + tid];
        m.x = fmaxf(m.x, v.x); m.y = fmaxf(m.y, v.y);
        m.z = fmaxf(m.z, v.z); m.w = fmaxf(m.w, v.w);
    }
    out[256 + tid] = m;
}

// ---- h1 GEMM (NT, split-K=16): partials ----
__global__ __launch_bounds__(256) void k_h1(const float* __restrict__ Wp1) {
    int ks = blockIdx.z;
    gemm128_body<true>(g_gold, Wp1, g_h1p + (size_t)ks * 512 * 256,
                       2048, 2048, 256,
                       blockIdx.y * 128, blockIdx.x * 128,
                       ks * 128, ks * 128 + 128, nullptr);
}

// ---- reduce h1 partials + bias, relu(LayerNorm) ----
__global__ __launch_bounds__(256) void k_ln(const float* __restrict__ bp1,
                                            const float* __restrict__ gamma,
                                            const float* __restrict__ beta) {
    __shared__ float red[256];
    int row = blockIdx.x, tid = threadIdx.x;
    float x = bp1[tid];
    #pragma unroll
    for (int p = 0; p < 16; p++) x += g_h1p[((size_t)p * 512 + row) * 256 + tid];
    red[tid] = x; __syncthreads();
    for (int s = 128; s > 0; s >>= 1) { if (tid < s) red[tid] += red[tid + s]; __syncthreads(); }
    float mean = red[0] * (1.0f / En); __syncthreads();
    float d = x - mean;
    red[tid] = d * d; __syncthreads();
    for (int s = 128; s > 0; s >>= 1) { if (tid < s) red[tid] += red[tid + s]; __syncthreads(); }
    float var = red[0] * (1.0f / En);
    float y = d * rsqrtf(var + 1e-5f) * gamma[tid] + beta[tid];
    g_h[(size_t)row * En + tid] = fmaxf(y, 0.f);
}

// ---- fused tail: h2 = h@Wp2^T+b2, logits = h2@Lab^T, log-softmax CE ----
// 8 rows per block (amortizes streaming Wp2 / label_embedding).
__global__ __launch_bounds__(256) void k_tail(const float* __restrict__ Wp2,
                                              const float* __restrict__ bp2,
                                              const float* __restrict__ lab,
                                              const int* __restrict__ chart,
                                              const int* __restrict__ action_len) {
    __shared__ float h[8][256];
    __shared__ float h2[8][256];
    __shared__ float lg[8][128];
    __shared__ float red[128];
    int tid = threadIdx.x;
    int r0 = blockIdx.x * 8;
    #pragma unroll
    for (int r = 0; r < 8; r++) h[r][tid] = g_h[(size_t)(r0 + r) * 256 + tid];
    __syncthreads();
    {
        float acc[8] = {0, 0, 0, 0, 0, 0, 0, 0};
        const float4* wr = reinterpret_cast<const float4*>(Wp2 + (size_t)tid * 256);
        for (int k = 0; k < 64; k++) {
            float4 w = wr[k];
            #pragma unroll
            for (int r = 0; r < 8; r++)
                acc[r] += w.x * h[r][4 * k] + w.y * h[r][4 * k + 1]
                        + w.z * h[r][4 * k + 2] + w.w * h[r][4 * k + 3];
        }
        float bb = bp2[tid];
        #pragma unroll
        for (int r = 0; r < 8; r++) h2[r][tid] = acc[r] + bb;
    }
    __syncthreads();
    if (tid < 128) {
        float acc[8] = {0, 0, 0, 0, 0, 0, 0, 0};
        const float4* lr = reinterpret_cast<const float4*>(lab + (size_t)tid * 256);
        for (int k = 0; k < 64; k++) {
            float4 w = lr[k];
            #pragma unroll
            for (int r = 0; r < 8; r++)
                acc[r] += w.x * h2[r][4 * k] + w.y * h2[r][4 * k + 1]
                        + w.z * h2[r][4 * k + 2] + w.w * h2[r][4 * k + 3];
        }
        #pragma unroll
        for (int r = 0; r < 8; r++) lg[r][tid] = acc[r];
    }
    __syncthreads();
    for (int r = 0; r < 8; r++) {
        if (tid < 128) red[tid] = lg[r][tid];
        __syncthreads();
        for (int s = 64; s > 0; s >>= 1) { if (tid < s) red[tid] = fmaxf(red[tid], red[tid + s]); __syncthreads(); }
        float mx = red[0]; __syncthreads();
        if (tid < 128) red[tid] = expf(lg[r][tid] - mx);
        __syncthreads();
        for (int s = 64; s > 0; s >>= 1) { if (tid < s) red[tid] += red[tid + s]; __syncthreads(); }
        if (tid == 0) {
            int row = r0 + r;
            int b = row >> 6, a = row & 63;
            float lse = logf(red[0]);
            float ce = -(lg[r][chart[row]] - mx - lse);
            g_ce_part[row] = (a < action_len[b]) ? ce : 0.f;
        }
        __syncthreads();
    }
}

// ---- final deterministic reduction ----
__global__ __launch_bounds__(512) void k_final(const int* __restrict__ action_len,
                                               float* __restrict__ out) {
    __shared__ float red[512];
    int tid = threadIdx.x;
    float num = (tid < 32 ? g_span_sum[tid] : 0.f) + (tid < 256 ? g_gold_part[tid] : 0.f);
    red[tid] = num; __syncthreads();
    for (int s = 256; s > 0; s >>= 1) { if (tid < s) red[tid] += red[tid + s]; __syncthreads(); }
    float span_num = red[0]; __syncthreads();

    red[tid] = (tid < 32 ? g_span_cnt2[tid] : 0.f); __syncthreads();
    for (int s = 256; s > 0; s >>= 1) { if (tid < s) red[tid] += red[tid + s]; __syncthreads(); }
    float span_cnt = red[0]; __syncthreads();

    red[tid] = g_ce_part[tid]; __syncthreads();
    for (int s = 256; s > 0; s >>= 1) { if (tid < s) red[tid] += red[tid + s]; __syncthreads(); }
    float ce_sum = red[0];

    if (tid == 0) {
        int lc = 0;
        for (int b = 0; b < Bn; b++) lc += action_len[b];
        out[0] = span_num / span_cnt + ce_sum / (float)lc;
    }
}

// =====================================================================
// Launch
// =====================================================================
extern "C" void kernel_launch(void* const* d_in, const int* in_sizes, int n_in,
                              void* d_out, int out_size) {
    const float* reprs      = (const float*)d_in[0];
    const float* word_repr  = (const float*)d_in[1];
    const int*   seq_len    = (const int*)d_in[2];
    const int*   gold_span  = (const int*)d_in[3];
    const int*   span_start = (const int*)d_in[4];
    const int*   span_end   = (const int*)d_in[5];
    const int*   chart      = (const int*)d_in[6];
    const int*   action_len = (const int*)d_in[7];
    const float* Wb         = (const float*)d_in[8];
    const float* Wp1        = (const float*)d_in[9];
    const float* bp1        = (const float*)d_in[10];
    const float* gamma      = (const float*)d_in[11];
    const float* beta       = (const float*)d_in[12];
    const float* Wp2        = (const float*)d_in[13];
    const float* bp2        = (const float*)d_in[14];
    const float* lab        = (const float*)d_in[15];
    float* out = (float*)d_out;

    // Biaffine path
    k_gemm1<<<dim3(8, 16), 256>>>(reprs, Wb);          // T main cols (128 blocks)
    k_bias_col<<<64, 256>>>(reprs, Wb);                // T[:,1024]
    k_span_g<<<dim3(2, 2, 32), 256>>>(reprs, seq_len); // split-K=4, ~96 live blocks
    k_span_epi<<<32, 256>>>(seq_len);                  // softplus + mask + count
    k_gold<<<256, 256>>>(reprs, gold_span, seq_len);   // warp per gold span

    // Label path
    k_gold_repr<<<Bn * An, 256>>>(reprs, word_repr, span_start, span_end);
    k_h1<<<dim3(2, 4, 16), 256>>>(Wp1);                // split-K=16 (128 blocks)
    k_ln<<<512, 256>>>(bp1, gamma, beta);              // partial-sum + bias + LN + relu
    k_tail<<<64, 256>>>(Wp2, bp2, lab, chart, action_len); // h2 + logits + CE fused

    k_final<<<1, 512>>>(action_len, out);
}

// round 4
// speedup vs baseline: 6.6008x; 1.7409x over previous
#include <cuda_runtime.h>
#include <cuda_bf16.h>
#include <math.h>
#include <stdint.h>

// Problem constants
#define Bn   8
#define Ln   256
#define Dn   1024
#define An   64
#define Vn   128
#define En   256
#define Gn   2048
#define Wn   255
#define NEGV (-1000.0f)

// bf16 pack/unpack
__device__ __forceinline__ uint32_t pk2(float a, float b) {
    __nv_bfloat162 h; h.x = __float2bfloat16(a); h.y = __float2bfloat16(b);
    return *reinterpret_cast<uint32_t*>(&h);
}
__device__ __forceinline__ float2 upk2(uint32_t u) {
    __nv_bfloat162 h = *reinterpret_cast<__nv_bfloat162*>(&u);
    return __bfloat1622float2(h);
}

// warp mma: D(16x8,f32) += A(16x16,bf16,row) * B(16x8,bf16,col)
__device__ __forceinline__ void mma16816(float d[4], uint32_t a0, uint32_t a1,
                                         uint32_t a2, uint32_t a3,
                                         uint32_t b0, uint32_t b1) {
    asm volatile(
        "mma.sync.aligned.m16n8k16.row.col.f32.bf16.bf16.f32 "
        "{%0,%1,%2,%3}, {%4,%5,%6,%7}, {%8,%9}, {%0,%1,%2,%3};\n"
        : "+f"(d[0]), "+f"(d[1]), "+f"(d[2]), "+f"(d[3])
        : "r"(a0), "r"(a1), "r"(a2), "r"(a3), "r"(b0), "r"(b1));
}

// ===================== device scratch =====================
__device__ __align__(16) __nv_bfloat16 g_reprs_b[Bn * Ln * Dn];   // 4 MB
__device__ __align__(16) __nv_bfloat16 g_word_b[Bn * Wn * Dn];    // ~4 MB
__device__ __align__(16) __nv_bfloat16 g_Wp1b[En * 2 * Dn];       // 1 MB
__device__ __align__(16) __nv_bfloat16 g_Wt[Dn * Dn];             // W^T bf16, 2 MB
__device__ __align__(16) __nv_bfloat16 g_Tb[Bn * Ln * Dn];        // T bf16, 4 MB
__device__ float g_Tbias[Bn * Ln];                                 // T[:,1024] fp32
__device__ __align__(16) __nv_bfloat16 g_goldb[Bn * An * 2 * Dn]; // 2 MB
__device__ float g_h1p[8 * 512 * 256];                             // h1 split-K partials
__device__ float g_h[512 * 256];
__device__ float g_span_sum[24];
__device__ float g_span_cnt2[24];
__device__ float g_gold_part[256];
__device__ float g_ce_part[512];

// ===================== conversions =====================
#define N_REPRS (Bn * Ln * Dn)        // 2097152
#define N_WORD  (Bn * Wn * Dn)        // 2088960
#define N_WP1   (En * 2 * Dn)         // 524288
__global__ __launch_bounds__(256) void k_convert(const float* __restrict__ reprs,
                                                 const float* __restrict__ word,
                                                 const float* __restrict__ wp1) {
    size_t i = ((size_t)blockIdx.x * 256 + threadIdx.x) * 8;
    const float* src; __nv_bfloat16* dst;
    if (i < N_REPRS) { src = reprs + i; dst = g_reprs_b + i; }
    else if (i < (size_t)N_REPRS + N_WORD) { size_t j = i - N_REPRS; src = word + j; dst = g_word_b + j; }
    else { size_t j = i - N_REPRS - N_WORD; src = wp1 + j; dst = g_Wp1b + j; }
    float4 a = *reinterpret_cast<const float4*>(src);
    float4 b = *reinterpret_cast<const float4*>(src + 4);
    uint4 o;
    o.x = pk2(a.x, a.y); o.y = pk2(a.z, a.w);
    o.z = pk2(b.x, b.y); o.w = pk2(b.z, b.w);
    *reinterpret_cast<uint4*>(dst) = o;
}

// W^T bf16 via shared-mem transpose, 64x64 tiles
__global__ __launch_bounds__(256) void k_wt(const float* __restrict__ Wb) {
    __shared__ float t[64][65];
    int n0 = blockIdx.x * 64, k0 = blockIdx.y * 64;
    int r = threadIdx.x >> 2, cq = (threadIdx.x & 3) * 16;
    #pragma unroll
    for (int i = 0; i < 16; i++)
        t[r][cq + i] = Wb[(size_t)(k0 + r) * 1025 + n0 + cq + i];
    __syncthreads();
    uint32_t pk[8];
    #pragma unroll
    for (int j = 0; j < 8; j++)
        pk[j] = pk2(t[cq + 2 * j][r], t[cq + 2 * j + 1][r]);
    __nv_bfloat16* dst = g_Wt + (size_t)(n0 + r) * 1024 + k0 + cq;
    *reinterpret_cast<uint4*>(dst)     = make_uint4(pk[0], pk[1], pk[2], pk[3]);
    *reinterpret_cast<uint4*>(dst + 8) = make_uint4(pk[4], pk[5], pk[6], pk[7]);
}

// ===================== HMMA NT mainloop =====================
// Block tile 128x128, 8 warps (2x4), warp tile 64x32, K-chunks of 32 bf16.
// Both A and B are K-contiguous (NT): C[m][n] = sum_k A[m][k]*B[n][k].
#define SD 40   // smem row stride in bf16 elements (80 B, conflict-free frags)

__device__ __forceinline__ void mma_nt_loop(
    const __nv_bfloat16* __restrict__ Ag, int lda, int m0,
    const __nv_bfloat16* __restrict__ Bg, int ldb, int n0,
    int kbeg, int kend, float acc[4][4][4])
{
    __shared__ __align__(16) __nv_bfloat16 As[2][128 * SD];
    __shared__ __align__(16) __nv_bfloat16 Bs[2][128 * SD];
    int tid = threadIdx.x;
    int lane = tid & 31, warp = tid >> 5;
    int wm = warp >> 2, wn = warp & 3;
    int g = lane >> 2, tg = lane & 3;
    int lr = tid >> 1, lq = (tid & 1) * 16;

    const __nv_bfloat16* Arow = Ag + (size_t)(m0 + lr) * lda + lq;
    const __nv_bfloat16* Brow = Bg + (size_t)(n0 + lr) * ldb + lq;

    int nc = (kend - kbeg) >> 5;
    {   // preload chunk 0
        uint4 va0 = *reinterpret_cast<const uint4*>(Arow + kbeg);
        uint4 va1 = *reinterpret_cast<const uint4*>(Arow + kbeg + 8);
        uint4 vb0 = *reinterpret_cast<const uint4*>(Brow + kbeg);
        uint4 vb1 = *reinterpret_cast<const uint4*>(Brow + kbeg + 8);
        *reinterpret_cast<uint4*>(&As[0][lr * SD + lq])     = va0;
        *reinterpret_cast<uint4*>(&As[0][lr * SD + lq + 8]) = va1;
        *reinterpret_cast<uint4*>(&Bs[0][lr * SD + lq])     = vb0;
        *reinterpret_cast<uint4*>(&Bs[0][lr * SD + lq + 8]) = vb1;
    }
    __syncthreads();
    for (int c = 0; c < nc; c++) {
        if (c + 1 < nc) {   // prefetch next chunk into the other buffer
            int kc = kbeg + (c + 1) * 32;
            uint4 va0 = *reinterpret_cast<const uint4*>(Arow + kc);
            uint4 va1 = *reinterpret_cast<const uint4*>(Arow + kc + 8);
            uint4 vb0 = *reinterpret_cast<const uint4*>(Brow + kc);
            uint4 vb1 = *reinterpret_cast<const uint4*>(Brow + kc + 8);
            int nb = (c + 1) & 1;
            *reinterpret_cast<uint4*>(&As[nb][lr * SD + lq])     = va0;
            *reinterpret_cast<uint4*>(&As[nb][lr * SD + lq + 8]) = va1;
            *reinterpret_cast<uint4*>(&Bs[nb][lr * SD + lq])     = vb0;
            *reinterpret_cast<uint4*>(&Bs[nb][lr * SD + lq + 8]) = vb1;
        }
        const __nv_bfloat16* as = As[c & 1];
        const __nv_bfloat16* bs = Bs[c & 1];
        #pragma unroll
        for (int kk = 0; kk < 32; kk += 16) {
            uint32_t af[4][4], bfr[4][2];
            #pragma unroll
            for (int mi = 0; mi < 4; mi++) {
                int bm = wm * 64 + mi * 16;
                af[mi][0] = *reinterpret_cast<const uint32_t*>(as + (bm + g) * SD + kk + 2 * tg);
                af[mi][1] = *reinterpret_cast<const uint32_t*>(as + (bm + g + 8) * SD + kk + 2 * tg);
                af[mi][2] = *reinterpret_cast<const uint32_t*>(as + (bm + g) * SD + kk + 2 * tg + 8);
                af[mi][3] = *reinterpret_cast<const uint32_t*>(as + (bm + g + 8) * SD + kk + 2 * tg + 8);
            }
            #pragma unroll
            for (int ni = 0; ni < 4; ni++) {
                int bn = wn * 32 + ni * 8;
                bfr[ni][0] = *reinterpret_cast<const uint32_t*>(bs + (bn + g) * SD + kk + 2 * tg);
                bfr[ni][1] = *reinterpret_cast<const uint32_t*>(bs + (bn + g) * SD + kk + 2 * tg + 8);
            }
            #pragma unroll
            for (int mi = 0; mi < 4; mi++)
                #pragma unroll
                for (int ni = 0; ni < 4; ni++)
                    mma16816(acc[mi][ni], af[mi][0], af[mi][1], af[mi][2], af[mi][3],
                             bfr[ni][0], bfr[ni][1]);
        }
        __syncthreads();
    }
}

// ---- GEMM1: T_bf16 = reprs_b @ Wt^T (+ bias row), M=2048, N=1024, K=1024 ----
__global__ __launch_bounds__(256) void k_gemm1_mma(const float* __restrict__ Wb) {
    float acc[4][4][4] = {};
    int m0 = blockIdx.y * 128, n0 = blockIdx.x * 128;
    mma_nt_loop(g_reprs_b, 1024, m0, g_Wt, 1024, n0, 0, 1024, acc);
    int lane = threadIdx.x & 31, warp = threadIdx.x >> 5;
    int wm = warp >> 2, wn = warp & 3, g = lane >> 2, tg = lane & 3;
    const float* brow = Wb + (size_t)1024 * 1025;
    #pragma unroll
    for (int mi = 0; mi < 4; mi++) {
        int m = m0 + wm * 64 + mi * 16 + g;
        #pragma unroll
        for (int ni = 0; ni < 4; ni++) {
            int n = n0 + wn * 32 + ni * 8 + 2 * tg;
            float b0 = brow[n], b1 = brow[n + 1];
            *reinterpret_cast<uint32_t*>(g_Tb + (size_t)m * 1024 + n) =
                pk2(acc[mi][ni][0] + b0, acc[mi][ni][1] + b1);
            *reinterpret_cast<uint32_t*>(g_Tb + (size_t)(m + 8) * 1024 + n) =
                pk2(acc[mi][ni][2] + b0, acc[mi][ni][3] + b1);
        }
    }
}

// ---- span GEMM + fused masked softplus epilogue ----
// grid (3, 8): t -> (x0,y0) in {(0,0),(0,128),(128,128)}, b = blockIdx.y
__global__ __launch_bounds__(256) void k_span_mma(const int* __restrict__ seq_len) {
    int t = blockIdx.x, b = blockIdx.y;
    int x0 = (t == 2) ? 128 : 0;
    int y0 = (t == 0) ? 0 : 128;
    int slot = b * 3 + t;
    int sl = seq_len[b];
    int tid = threadIdx.x;
    __shared__ float red[256];
    if (y0 > sl) {
        if (tid == 0) { g_span_sum[slot] = 0.f; g_span_cnt2[slot] = 0.f; }
        return;
    }
    float acc[4][4][4] = {};
    mma_nt_loop(g_Tb + (size_t)b * Ln * Dn, 1024, x0,
                g_reprs_b + (size_t)b * Ln * Dn, 1024, y0, 0, 1024, acc);
    int lane = tid & 31, warp = tid >> 5;
    int wm = warp >> 2, wn = warp & 3, g = lane >> 2, tg = lane & 3;
    float lsum = 0.f, lcnt = 0.f;
    #pragma unroll
    for (int mi = 0; mi < 4; mi++) {
        int xA = x0 + wm * 64 + mi * 16 + g;
        int xB = xA + 8;
        float tbA = g_Tbias[b * Ln + xA];
        float tbB = g_Tbias[b * Ln + xB];
        #pragma unroll
        for (int ni = 0; ni < 4; ni++) {
            int y = y0 + wn * 32 + ni * 8 + 2 * tg;
            #pragma unroll
            for (int e = 0; e < 4; e++) {
                int yy = y + (e & 1);
                int xx = (e < 2) ? xA : xB;
                float tb = (e < 2) ? tbA : tbB;
                if (yy > xx && yy <= sl) {
                    float s = acc[mi][ni][e] + tb;
                    lsum += fmaxf(s, 0.f) + log1pf(expf(-fabsf(s)));
                    lcnt += 1.f;
                }
            }
        }
    }
    red[tid] = lsum; __syncthreads();
    for (int s = 128; s > 0; s >>= 1) { if (tid < s) red[tid] += red[tid + s]; __syncthreads(); }
    float tot = red[0]; __syncthreads();
    red[tid] = lcnt; __syncthreads();
    for (int s = 128; s > 0; s >>= 1) { if (tid < s) red[tid] += red[tid + s]; __syncthreads(); }
    if (tid == 0) { g_span_sum[slot] = tot; g_span_cnt2[slot] = red[0]; }
}

// ---- h1 split-K=8: partials[ks] = gold_b @ Wp1_b^T over K slice ----
__global__ __launch_bounds__(256) void k_h1_mma() {
    float acc[4][4][4] = {};
    int n0 = blockIdx.x * 128, m0 = blockIdx.y * 128, ks = blockIdx.z;
    mma_nt_loop(g_goldb, 2048, m0, g_Wp1b, 2048, n0, ks * 256, ks * 256 + 256, acc);
    int lane = threadIdx.x & 31, warp = threadIdx.x >> 5;
    int wm = warp >> 2, wn = warp & 3, g = lane >> 2, tg = lane & 3;
    float* dst = g_h1p + (size_t)ks * 512 * 256;
    #pragma unroll
    for (int mi = 0; mi < 4; mi++) {
        int m = m0 + wm * 64 + mi * 16 + g;
        #pragma unroll
        for (int ni = 0; ni < 4; ni++) {
            int n = n0 + wn * 32 + ni * 8 + 2 * tg;
            *reinterpret_cast<float2*>(dst + (size_t)m * 256 + n) =
                make_float2(acc[mi][ni][0], acc[mi][ni][1]);
            *reinterpret_cast<float2*>(dst + (size_t)(m + 8) * 256 + n) =
                make_float2(acc[mi][ni][2], acc[mi][ni][3]);
        }
    }
}

// ===================== non-tensor kernels =====================

// T bias column (fp32): g_Tbias[row] = reprs[row]·W[:,1024] + W[1024,1024]
__global__ __launch_bounds__(256) void k_bias_col(const float* __restrict__ A,
                                                  const float* __restrict__ Wb) {
    __shared__ float wcol[1024];
    for (int i = threadIdx.x; i < 1024; i += 256) wcol[i] = Wb[(size_t)i * 1025 + 1024];
    __syncthreads();
    int wid = threadIdx.x >> 5, lane = threadIdx.x & 31;
    float wbias = Wb[(size_t)1024 * 1025 + 1024];
    #pragma unroll
    for (int rr = 0; rr < 4; rr++) {
        int row = blockIdx.x * 32 + wid * 4 + rr;
        const float* ar = A + (size_t)row * 1024;
        float s = 0.f;
        for (int j = lane * 4; j < 1024; j += 128) {
            float4 a = *reinterpret_cast<const float4*>(ar + j);
            s += a.x * wcol[j] + a.y * wcol[j + 1] + a.z * wcol[j + 2] + a.w * wcol[j + 3];
        }
        #pragma unroll
        for (int o = 16; o; o >>= 1) s += __shfl_xor_sync(0xffffffff, s, o);
        if (lane == 0) g_Tbias[row] = s + wbias;
    }
}

// gold spans: warp per span, lane-parallel dedup, -s[gold] (bf16 dot)
__global__ __launch_bounds__(256) void k_gold(const int* __restrict__ gold,
                                              const int* __restrict__ seq_len) {
    __shared__ float wsum[8];
    int wid = threadIdx.x >> 5, lane = threadIdx.x & 31;
    int g = blockIdx.x * 8 + wid;
    float val = 0.f;
    int gb = gold[3 * g], gl = gold[3 * g + 1], gr = gold[3 * g + 2];
    if (gr > gl && gr <= seq_len[gb]) {
        int key = (gb << 16) | (gl << 8) | gr;
        bool dup = false;
        for (int p = lane; p < g; p += 32) {
            int k2 = (gold[3 * p] << 16) | (gold[3 * p + 1] << 8) | gold[3 * p + 2];
            if (k2 == key) dup = true;
        }
        dup = __any_sync(0xffffffff, dup);
        if (!dup) {
            const __nv_bfloat16* tr = g_Tb + (size_t)(gb * Ln + gl) * Dn;
            const __nv_bfloat16* rr = g_reprs_b + (size_t)(gb * Ln + gr) * Dn;
            float s = 0.f;
            for (int j = lane * 8; j < 1024; j += 256) {
                uint4 tv = *reinterpret_cast<const uint4*>(tr + j);
                uint4 rv = *reinterpret_cast<const uint4*>(rr + j);
                float2 t0 = upk2(tv.x), t1 = upk2(tv.y), t2 = upk2(tv.z), t3 = upk2(tv.w);
                float2 r0 = upk2(rv.x), r1 = upk2(rv.y), r2 = upk2(rv.z), r3 = upk2(rv.w);
                s += t0.x * r0.x + t0.y * r0.y + t1.x * r1.x + t1.y * r1.y
                   + t2.x * r2.x + t2.y * r2.y + t3.x * r3.x + t3.y * r3.y;
            }
            #pragma unroll
            for (int o = 16; o; o >>= 1) s += __shfl_xor_sync(0xffffffff, s, o);
            if (lane == 0) val = -(s + g_Tbias[gb * Ln + gl]);
        }
    }
    if (lane == 0) wsum[wid] = val;
    __syncthreads();
    if (threadIdx.x == 0) {
        float t = 0.f;
        #pragma unroll
        for (int i = 0; i < 8; i++) t += wsum[i];
        g_gold_part[blockIdx.x] = t;
    }
}

// gold_repr (bf16) = concat(end-start, maxpool word_repr[start:end))
__global__ __launch_bounds__(256) void k_gold_repr(const float* __restrict__ reprs,
                                                   const int* __restrict__ span_start,
                                                   const int* __restrict__ span_end) {
    int row = blockIdx.x, tid = threadIdx.x;
    int b = row >> 6;
    int s = span_start[row], e = span_end[row];
    const float4* rs = reinterpret_cast<const float4*>(reprs + ((size_t)b * Ln + s) * Dn);
    const float4* re = reinterpret_cast<const float4*>(reprs + ((size_t)b * Ln + e) * Dn);
    float4 a = re[tid], c = rs[tid];
    uint2 o;
    o.x = pk2(a.x - c.x, a.y - c.y);
    o.y = pk2(a.z - c.z, a.w - c.w);
    *reinterpret_cast<uint2*>(g_goldb + (size_t)row * 2048 + tid * 4) = o;

    float m0 = NEGV, m1 = NEGV, m2 = NEGV, m3 = NEGV;
    const __nv_bfloat16* wb = g_word_b + (size_t)b * Wn * Dn + tid * 4;
    int ee = min(e, Wn);
    for (int w = s; w < ee; w++) {
        uint2 v = *reinterpret_cast<const uint2*>(wb + (size_t)w * Dn);
        float2 f0 = upk2(v.x), f1 = upk2(v.y);
        m0 = fmaxf(m0, f0.x); m1 = fmaxf(m1, f0.y);
        m2 = fmaxf(m2, f1.x); m3 = fmaxf(m3, f1.y);
    }
    uint2 p; p.x = pk2(m0, m1); p.y = pk2(m2, m3);
    *reinterpret_cast<uint2*>(g_goldb + (size_t)row * 2048 + 1024 + tid * 4) = p;
}

// reduce h1 partials + bias, relu(LayerNorm)
__global__ __launch_bounds__(256) void k_ln(const float* __restrict__ bp1,
                                            const float* __restrict__ gamma,
                                            const float* __restrict__ beta) {
    __shared__ float red[256];
    int row = blockIdx.x, tid = threadIdx.x;
    float x = bp1[tid];
    #pragma unroll
    for (int p = 0; p < 8; p++) x += g_h1p[((size_t)p * 512 + row) * 256 + tid];
    red[tid] = x; __syncthreads();
    for (int s = 128; s > 0; s >>= 1) { if (tid < s) red[tid] += red[tid + s]; __syncthreads(); }
    float mean = red[0] * (1.0f / En); __syncthreads();
    float d = x - mean;
    red[tid] = d * d; __syncthreads();
    for (int s = 128; s > 0; s >>= 1) { if (tid < s) red[tid] += red[tid + s]; __syncthreads(); }
    float var = red[0] * (1.0f / En);
    float y = d * rsqrtf(var + 1e-5f) * gamma[tid] + beta[tid];
    g_h[(size_t)row * En + tid] = fmaxf(y, 0.f);
}

// fused tail: h2 = h@Wp2^T+b2, logits = h2@Lab^T, log-softmax CE
__global__ __launch_bounds__(256) void k_tail(const float* __restrict__ Wp2,
                                              const float* __restrict__ bp2,
                                              const float* __restrict__ lab,
                                              const int* __restrict__ chart,
                                              const int* __restrict__ action_len) {
    __shared__ float h[8][256];
    __shared__ float h2[8][256];
    __shared__ float lg[8][128];
    __shared__ float red[128];
    int tid = threadIdx.x;
    int r0 = blockIdx.x * 8;
    #pragma unroll
    for (int r = 0; r < 8; r++) h[r][tid] = g_h[(size_t)(r0 + r) * 256 + tid];
    __syncthreads();
    {
        float acc[8] = {0, 0, 0, 0, 0, 0, 0, 0};
        const float4* wr = reinterpret_cast<const float4*>(Wp2 + (size_t)tid * 256);
        for (int k = 0; k < 64; k++) {
            float4 w = wr[k];
            #pragma unroll
            for (int r = 0; r < 8; r++)
                acc[r] += w.x * h[r][4 * k] + w.y * h[r][4 * k + 1]
                        + w.z * h[r][4 * k + 2] + w.w * h[r][4 * k + 3];
        }
        float bb = bp2[tid];
        #pragma unroll
        for (int r = 0; r < 8; r++) h2[r][tid] = acc[r] + bb;
    }
    __syncthreads();
    if (tid < 128) {
        float acc[8] = {0, 0, 0, 0, 0, 0, 0, 0};
        const float4* lr = reinterpret_cast<const float4*>(lab + (size_t)tid * 256);
        for (int k = 0; k < 64; k++) {
            float4 w = lr[k];
            #pragma unroll
            for (int r = 0; r < 8; r++)
                acc[r] += w.x * h2[r][4 * k] + w.y * h2[r][4 * k + 1]
                        + w.z * h2[r][4 * k + 2] + w.w * h2[r][4 * k + 3];
        }
        #pragma unroll
        for (int r = 0; r < 8; r++) lg[r][tid] = acc[r];
    }
    __syncthreads();
    for (int r = 0; r < 8; r++) {
        if (tid < 128) red[tid] = lg[r][tid];
        __syncthreads();
        for (int s = 64; s > 0; s >>= 1) { if (tid < s) red[tid] = fmaxf(red[tid], red[tid + s]); __syncthreads(); }
        float mx = red[0]; __syncthreads();
        if (tid < 128) red[tid] = expf(lg[r][tid] - mx);
        __syncthreads();
        for (int s = 64; s > 0; s >>= 1) { if (tid < s) red[tid] += red[tid + s]; __syncthreads(); }
        if (tid == 0) {
            int row = r0 + r;
            int b = row >> 6, a = row & 63;
            float lse = logf(red[0]);
            float ce = -(lg[r][chart[row]] - mx - lse);
            g_ce_part[row] = (a < action_len[b]) ? ce : 0.f;
        }
        __syncthreads();
    }
}

// final deterministic reduction
__global__ __launch_bounds__(512) void k_final(const int* __restrict__ action_len,
                                               float* __restrict__ out) {
    __shared__ float red[512];
    int tid = threadIdx.x;
    float num = (tid < 24 ? g_span_sum[tid] : 0.f) + (tid < 256 ? g_gold_part[tid] : 0.f);
    red[tid] = num; __syncthreads();
    for (int s = 256; s > 0; s >>= 1) { if (tid < s) red[tid] += red[tid + s]; __syncthreads(); }
    float span_num = red[0]; __syncthreads();

    red[tid] = (tid < 24 ? g_span_cnt2[tid] : 0.f); __syncthreads();
    for (int s = 256; s > 0; s >>= 1) { if (tid < s) red[tid] += red[tid + s]; __syncthreads(); }
    float span_cnt = red[0]; __syncthreads();

    red[tid] = g_ce_part[tid]; __syncthreads();
    for (int s = 256; s > 0; s >>= 1) { if (tid < s) red[tid] += red[tid + s]; __syncthreads(); }
    float ce_sum = red[0];

    if (tid == 0) {
        int lc = 0;
        for (int b = 0; b < Bn; b++) lc += action_len[b];
        out[0] = span_num / span_cnt + ce_sum / (float)lc;
    }
}

// ===================== launch =====================
extern "C" void kernel_launch(void* const* d_in, const int* in_sizes, int n_in,
                              void* d_out, int out_size) {
    const float* reprs      = (const float*)d_in[0];
    const float* word_repr  = (const float*)d_in[1];
    const int*   seq_len    = (const int*)d_in[2];
    const int*   gold_span  = (const int*)d_in[3];
    const int*   span_start = (const int*)d_in[4];
    const int*   span_end   = (const int*)d_in[5];
    const int*   chart      = (const int*)d_in[6];
    const int*   action_len = (const int*)d_in[7];
    const float* Wb         = (const float*)d_in[8];
    const float* Wp1        = (const float*)d_in[9];
    const float* bp1        = (const float*)d_in[10];
    const float* gamma      = (const float*)d_in[11];
    const float* beta       = (const float*)d_in[12];
    const float* Wp2        = (const float*)d_in[13];
    const float* bp2        = (const float*)d_in[14];
    const float* lab        = (const float*)d_in[15];
    float* out = (float*)d_out;

    // conversions + W transpose + bias column
    k_convert<<<2300, 256>>>(reprs, word_repr, Wp1);
    k_wt<<<dim3(16, 16), 256>>>(Wb);
    k_bias_col<<<64, 256>>>(reprs, Wb);

    // tensor-core (HMMA) GEMMs
    k_gemm1_mma<<<dim3(8, 16), 256>>>(Wb);             // T bf16 (bias row fused)
    k_span_mma<<<dim3(3, 8), 256>>>(seq_len);          // fused masked softplus
    k_gold<<<256, 256>>>(gold_span, seq_len);          // gold dots (bf16)

    // label path
    k_gold_repr<<<Bn * An, 256>>>(reprs, span_start, span_end);
    k_h1_mma<<<dim3(2, 4, 8), 256>>>();                // split-K=8
    k_ln<<<512, 256>>>(bp1, gamma, beta);
    k_tail<<<64, 256>>>(Wp2, bp2, lab, chart, action_len);

    k_final<<<1, 512>>>(action_len, out);
}

// round 7
// speedup vs baseline: 8.7662x; 1.3280x over previous
// R7: resubmission of the R5/R6 cp.async+ldmatrix HMMA design.
// R0 established "container failed twice" occurs with an empty stub -> infra-side.
#include <cuda_runtime.h>
#include <cuda_bf16.h>
#include <math.h>
#include <stdint.h>

// Problem constants
#define Bn   8
#define Ln   256
#define Dn   1024
#define An   64
#define Vn   128
#define En   256
#define Gn   2048
#define Wn   255
#define NEGV (-1000.0f)

// bf16 pack/unpack
__device__ __forceinline__ uint32_t pk2(float a, float b) {
    __nv_bfloat162 h; h.x = __float2bfloat16(a); h.y = __float2bfloat16(b);
    return *reinterpret_cast<uint32_t*>(&h);
}
__device__ __forceinline__ float2 upk2(uint32_t u) {
    __nv_bfloat162 h = *reinterpret_cast<__nv_bfloat162*>(&u);
    return __bfloat1622float2(h);
}
__device__ __forceinline__ uint32_t sm_u32(const void* p) {
    uint32_t a;
    asm("{ .reg .u64 t; cvta.to.shared.u64 t, %1; cvt.u32.u64 %0, t; }" : "=r"(a) : "l"(p));
    return a;
}

// warp mma: D(16x8,f32) += A(16x16,bf16,row) * B(16x8,bf16,col)
__device__ __forceinline__ void mma16816(float d[4], uint32_t a0, uint32_t a1,
                                         uint32_t a2, uint32_t a3,
                                         uint32_t b0, uint32_t b1) {
    asm volatile(
        "mma.sync.aligned.m16n8k16.row.col.f32.bf16.bf16.f32 "
        "{%0,%1,%2,%3}, {%4,%5,%6,%7}, {%8,%9}, {%0,%1,%2,%3};\n"
        : "+f"(d[0]), "+f"(d[1]), "+f"(d[2]), "+f"(d[3])
        : "r"(a0), "r"(a1), "r"(a2), "r"(a3), "r"(b0), "r"(b1));
}
__device__ __forceinline__ void ldsm_x4(uint32_t r[4], uint32_t addr) {
    asm volatile("ldmatrix.sync.aligned.m8n8.x4.shared.b16 {%0,%1,%2,%3}, [%4];\n"
                 : "=r"(r[0]), "=r"(r[1]), "=r"(r[2]), "=r"(r[3]) : "r"(addr));
}
__device__ __forceinline__ void cp16(uint32_t s_dst, const void* g_src) {
    asm volatile("cp.async.cg.shared.global [%0], [%1], 16;\n" :: "r"(s_dst), "l"(g_src));
}
#define CP_COMMIT() asm volatile("cp.async.commit_group;\n" ::: "memory")
#define CP_WAIT0()  asm volatile("cp.async.wait_group 0;\n" ::: "memory")
#define CP_WAIT1()  asm volatile("cp.async.wait_group 1;\n" ::: "memory")

// ===================== device scratch =====================
__device__ __align__(16) __nv_bfloat16 g_reprs_b[Bn * Ln * Dn];   // 4 MB
__device__ __align__(16) __nv_bfloat16 g_word_b[Bn * Wn * Dn];    // ~4 MB
__device__ __align__(16) __nv_bfloat16 g_Wp1b[En * 2 * Dn];       // 1 MB
__device__ __align__(16) __nv_bfloat16 g_Wt[Dn * Dn];             // W^T bf16, 2 MB
__device__ __align__(16) __nv_bfloat16 g_Tb[Bn * Ln * Dn];        // T bf16, 4 MB
__device__ float g_Tbias[Bn * Ln];                                 // T[:,1024] fp32
__device__ __align__(16) __nv_bfloat16 g_goldb[Bn * An * 2 * Dn]; // 2 MB
__device__ float g_h1p[8 * 512 * 256];                             // h1 split-K partials
__device__ float g_h[512 * 256];
__device__ float g_span_sum[80];
__device__ float g_span_cnt2[80];
__device__ float g_gold_part[256];
__device__ float g_ce_part[512];

// ===================== conversions =====================
#define N_REPRS (Bn * Ln * Dn)        // 2097152
#define N_WORD  (Bn * Wn * Dn)        // 2088960
#define N_WP1   (En * 2 * Dn)         // 524288
__global__ __launch_bounds__(256) void k_convert(const float* __restrict__ reprs,
                                                 const float* __restrict__ word,
                                                 const float* __restrict__ wp1) {
    size_t i = ((size_t)blockIdx.x * 256 + threadIdx.x) * 8;
    const float* src; __nv_bfloat16* dst;
    if (i < N_REPRS) { src = reprs + i; dst = g_reprs_b + i; }
    else if (i < (size_t)N_REPRS + N_WORD) { size_t j = i - N_REPRS; src = word + j; dst = g_word_b + j; }
    else { size_t j = i - N_REPRS - N_WORD; src = wp1 + j; dst = g_Wp1b + j; }
    float4 a = *reinterpret_cast<const float4*>(src);
    float4 b = *reinterpret_cast<const float4*>(src + 4);
    uint4 o;
    o.x = pk2(a.x, a.y); o.y = pk2(a.z, a.w);
    o.z = pk2(b.x, b.y); o.w = pk2(b.z, b.w);
    *reinterpret_cast<uint4*>(dst) = o;
}

// W^T bf16 via shared-mem transpose, 64x64 tiles
__global__ __launch_bounds__(256) void k_wt(const float* __restrict__ Wb) {
    __shared__ float t[64][65];
    int n0 = blockIdx.x * 64, k0 = blockIdx.y * 64;
    int r = threadIdx.x >> 2, cq = (threadIdx.x & 3) * 16;
    #pragma unroll
    for (int i = 0; i < 16; i++)
        t[r][cq + i] = Wb[(size_t)(k0 + r) * 1025 + n0 + cq + i];
    __syncthreads();
    uint32_t pk[8];
    #pragma unroll
    for (int j = 0; j < 8; j++)
        pk[j] = pk2(t[cq + 2 * j][r], t[cq + 2 * j + 1][r]);
    __nv_bfloat16* dst = g_Wt + (size_t)(n0 + r) * 1024 + k0 + cq;
    *reinterpret_cast<uint4*>(dst)     = make_uint4(pk[0], pk[1], pk[2], pk[3]);
    *reinterpret_cast<uint4*>(dst + 8) = make_uint4(pk[4], pk[5], pk[6], pk[7]);
}

// ===================== HMMA NT mainloop (cp.async + ldmatrix) =====================
// Template: block tile BM x BN, 8 warps, warp tile (16*MI) x (8*NI).
// Warp grid: WR = BM/(16*MI) rows x WC = BN/(8*NI) cols, WR*WC == 8, 256 threads.
// K-chunks of 32 bf16, double-buffered via cp.async.
#define SD 40   // smem row stride in bf16 (80 B): conflict-free ldmatrix gathers

template<int BM, int BN, int MI, int NI>
__device__ __forceinline__ void mma_nt_loop(
    const __nv_bfloat16* __restrict__ Ag, int lda, int m0,
    const __nv_bfloat16* __restrict__ Bg, int ldb, int n0,
    int kbeg, int kend, float acc[MI][NI][4],
    __nv_bfloat16* As, __nv_bfloat16* Bs)   // [2][BM*SD], [2][BN*SD]
{
    constexpr int WC = BN / (8 * NI);
    int tid = threadIdx.x;
    int lane = tid & 31, warp = tid >> 5;
    int wm = warp / WC, wn = warp % WC;

    // cp.async addressing: row = idx>>2, 16B segment = idx&3
    int ldr = tid >> 2, lds_ = (tid & 3) * 8;
    const __nv_bfloat16* Arow = Ag + (size_t)(m0 + ldr) * lda + lds_;
    const __nv_bfloat16* Brow = Bg + (size_t)(n0 + ldr) * ldb + lds_;
    uint32_t sa_st = sm_u32(As + ldr * SD + lds_);
    uint32_t sb_st = sm_u32(Bs + ldr * SD + lds_);
    constexpr int AIT = (BM * 4) / 256;   // cp16 iters for A (64 rows per iter)
    constexpr int BIT = (BN * 4) / 256;
    constexpr uint32_t stgA = (uint32_t)(BM * SD * 2);
    constexpr uint32_t stgB = (uint32_t)(BN * SD * 2);

    // ldmatrix base addresses (stage 0)
    // A: row = wm*MI*16 + mi*16 + (lane&15), col = 8*(lane>>4)
    uint32_t a_ld0 = sm_u32(As + (wm * MI * 16 + (lane & 15)) * SD + 8 * (lane >> 4));
    // B: row = wn*NI*8 + nj*16 + (lane&7) + 8*(lane>>4), col = 8*((lane>>3)&1)
    uint32_t b_ld0 = sm_u32(Bs + (wn * NI * 8 + (lane & 7) + 8 * (lane >> 4)) * SD
                            + 8 * ((lane >> 3) & 1));

    int nc = (kend - kbeg) >> 5;
    // preload chunk 0 into stage 0
    #pragma unroll
    for (int it = 0; it < AIT; it++)
        cp16(sa_st + it * (64 * SD * 2), Arow + (size_t)it * 64 * lda + kbeg);
    #pragma unroll
    for (int it = 0; it < BIT; it++)
        cp16(sb_st + it * (64 * SD * 2), Brow + (size_t)it * 64 * ldb + kbeg);
    CP_COMMIT();

    for (int c = 0; c < nc; c++) {
        if (c + 1 < nc) {
            int kc = kbeg + (c + 1) * 32;
            uint32_t oa = ((c + 1) & 1) ? stgA : 0u;
            uint32_t ob = ((c + 1) & 1) ? stgB : 0u;
            #pragma unroll
            for (int it = 0; it < AIT; it++)
                cp16(sa_st + oa + it * (64 * SD * 2), Arow + (size_t)it * 64 * lda + kc);
            #pragma unroll
            for (int it = 0; it < BIT; it++)
                cp16(sb_st + ob + it * (64 * SD * 2), Brow + (size_t)it * 64 * ldb + kc);
            CP_COMMIT();
            CP_WAIT1();
        } else {
            CP_WAIT0();
        }
        __syncthreads();
        uint32_t a_ld = a_ld0 + ((c & 1) ? stgA : 0u);
        uint32_t b_ld = b_ld0 + ((c & 1) ? stgB : 0u);
        #pragma unroll
        for (int kk = 0; kk < 2; kk++) {           // two k16 steps, +32 B each
            uint32_t af[MI][4], bfr[NI][2];
            #pragma unroll
            for (int mi = 0; mi < MI; mi++)
                ldsm_x4(af[mi], a_ld + kk * 32 + mi * (16 * SD * 2));
            #pragma unroll
            for (int nj = 0; nj < NI / 2; nj++) {
                uint32_t br[4];
                ldsm_x4(br, b_ld + kk * 32 + nj * (16 * SD * 2));
                bfr[2 * nj][0] = br[0]; bfr[2 * nj][1] = br[1];
                bfr[2 * nj + 1][0] = br[2]; bfr[2 * nj + 1][1] = br[3];
            }
            #pragma unroll
            for (int mi = 0; mi < MI; mi++)
                #pragma unroll
                for (int ni = 0; ni < NI; ni++)
                    mma16816(acc[mi][ni], af[mi][0], af[mi][1], af[mi][2], af[mi][3],
                             bfr[ni][0], bfr[ni][1]);
        }
        __syncthreads();
    }
}

// ---- GEMM1: T_bf16 = reprs_b @ Wt^T (+ bias row), M=2048, N=1024, K=1024 ----
__global__ __launch_bounds__(256) void k_gemm1_mma(const float* __restrict__ Wb) {
    __shared__ __align__(16) __nv_bfloat16 As[2 * 128 * SD];
    __shared__ __align__(16) __nv_bfloat16 Bs[2 * 128 * SD];
    float acc[4][4][4] = {};
    int m0 = blockIdx.y * 128, n0 = blockIdx.x * 128;
    mma_nt_loop<128, 128, 4, 4>(g_reprs_b, 1024, m0, g_Wt, 1024, n0, 0, 1024, acc, As, Bs);
    int lane = threadIdx.x & 31, warp = threadIdx.x >> 5;
    int wm = warp >> 2, wn = warp & 3, g = lane >> 2, tg = lane & 3;
    const float* brow = Wb + (size_t)1024 * 1025;
    #pragma unroll
    for (int mi = 0; mi < 4; mi++) {
        int m = m0 + wm * 64 + mi * 16 + g;
        #pragma unroll
        for (int ni = 0; ni < 4; ni++) {
            int n = n0 + wn * 32 + ni * 8 + 2 * tg;
            float b0 = brow[n], b1 = brow[n + 1];
            *reinterpret_cast<uint32_t*>(g_Tb + (size_t)m * 1024 + n) =
                pk2(acc[mi][ni][0] + b0, acc[mi][ni][1] + b1);
            *reinterpret_cast<uint32_t*>(g_Tb + (size_t)(m + 8) * 1024 + n) =
                pk2(acc[mi][ni][2] + b0, acc[mi][ni][3] + b1);
        }
    }
}

// ---- span GEMM 64x64 tiles + fused masked softplus epilogue ----
// grid (10, 8): upper-triangle tile list, b = blockIdx.y
__constant__ int c_xt[10] = {0, 0, 0, 0, 1, 1, 1, 2, 2, 3};
__constant__ int c_yt[10] = {0, 1, 2, 3, 1, 2, 3, 2, 3, 3};
__global__ __launch_bounds__(256) void k_span_mma(const int* __restrict__ seq_len) {
    __shared__ __align__(16) __nv_bfloat16 As[2 * 64 * SD];
    __shared__ __align__(16) __nv_bfloat16 Bs[2 * 64 * SD];
    __shared__ float red[256];
    int t = blockIdx.x, b = blockIdx.y;
    int x0 = c_xt[t] * 64, y0 = c_yt[t] * 64;
    int slot = b * 10 + t;
    int sl = seq_len[b];
    int tid = threadIdx.x;
    if (y0 > sl) {
        if (tid == 0) { g_span_sum[slot] = 0.f; g_span_cnt2[slot] = 0.f; }
        return;
    }
    // 8 warps 2x4, warp tile 32x16: MI=2, NI=2
    float acc[2][2][4] = {};
    mma_nt_loop<64, 64, 2, 2>(g_Tb + (size_t)b * Ln * Dn, 1024, x0,
                              g_reprs_b + (size_t)b * Ln * Dn, 1024, y0, 0, 1024, acc, As, Bs);
    int lane = tid & 31, warp = tid >> 5;
    int wm = warp >> 2, wn = warp & 3, g = lane >> 2, tg = lane & 3;
    float lsum = 0.f, lcnt = 0.f;
    #pragma unroll
    for (int mi = 0; mi < 2; mi++) {
        int xA = x0 + wm * 32 + mi * 16 + g;
        int xB = xA + 8;
        float tbA = g_Tbias[b * Ln + xA];
        float tbB = g_Tbias[b * Ln + xB];
        #pragma unroll
        for (int ni = 0; ni < 2; ni++) {
            int y = y0 + wn * 16 + ni * 8 + 2 * tg;
            #pragma unroll
            for (int e = 0; e < 4; e++) {
                int yy = y + (e & 1);
                int xx = (e < 2) ? xA : xB;
                float tb = (e < 2) ? tbA : tbB;
                if (yy > xx && yy <= sl) {
                    float s = acc[mi][ni][e] + tb;
                    lsum += fmaxf(s, 0.f) + log1pf(expf(-fabsf(s)));
                    lcnt += 1.f;
                }
            }
        }
    }
    red[tid] = lsum; __syncthreads();
    for (int s = 128; s > 0; s >>= 1) { if (tid < s) red[tid] += red[tid + s]; __syncthreads(); }
    float tot = red[0]; __syncthreads();
    red[tid] = lcnt; __syncthreads();
    for (int s = 128; s > 0; s >>= 1) { if (tid < s) red[tid] += red[tid + s]; __syncthreads(); }
    if (tid == 0) { g_span_sum[slot] = tot; g_span_cnt2[slot] = red[0]; }
}

// ---- h1 split-K=8: partials[ks] = gold_b @ Wp1_b^T over K slice ----
__global__ __launch_bounds__(256) void k_h1_mma() {
    __shared__ __align__(16) __nv_bfloat16 As[2 * 128 * SD];
    __shared__ __align__(16) __nv_bfloat16 Bs[2 * 128 * SD];
    float acc[4][4][4] = {};
    int n0 = blockIdx.x * 128, m0 = blockIdx.y * 128, ks = blockIdx.z;
    mma_nt_loop<128, 128, 4, 4>(g_goldb, 2048, m0, g_Wp1b, 2048, n0,
                                ks * 256, ks * 256 + 256, acc, As, Bs);
    int lane = threadIdx.x & 31, warp = threadIdx.x >> 5;
    int wm = warp >> 2, wn = warp & 3, g = lane >> 2, tg = lane & 3;
    float* dst = g_h1p + (size_t)ks * 512 * 256;
    #pragma unroll
    for (int mi = 0; mi < 4; mi++) {
        int m = m0 + wm * 64 + mi * 16 + g;
        #pragma unroll
        for (int ni = 0; ni < 4; ni++) {
            int n = n0 + wn * 32 + ni * 8 + 2 * tg;
            *reinterpret_cast<float2*>(dst + (size_t)m * 256 + n) =
                make_float2(acc[mi][ni][0], acc[mi][ni][1]);
            *reinterpret_cast<float2*>(dst + (size_t)(m + 8) * 256 + n) =
                make_float2(acc[mi][ni][2], acc[mi][ni][3]);
        }
    }
}

// ===================== non-tensor kernels =====================

// T bias column (fp32): g_Tbias[row] = reprs[row]·W[:,1024] + W[1024,1024]
__global__ __launch_bounds__(256) void k_bias_col(const float* __restrict__ A,
                                                  const float* __restrict__ Wb) {
    __shared__ float wcol[1024];
    for (int i = threadIdx.x; i < 1024; i += 256) wcol[i] = Wb[(size_t)i * 1025 + 1024];
    __syncthreads();
    int wid = threadIdx.x >> 5, lane = threadIdx.x & 31;
    float wbias = Wb[(size_t)1024 * 1025 + 1024];
    #pragma unroll
    for (int rr = 0; rr < 4; rr++) {
        int row = blockIdx.x * 32 + wid * 4 + rr;
        const float* ar = A + (size_t)row * 1024;
        float s = 0.f;
        for (int j = lane * 4; j < 1024; j += 128) {
            float4 a = *reinterpret_cast<const float4*>(ar + j);
            s += a.x * wcol[j] + a.y * wcol[j + 1] + a.z * wcol[j + 2] + a.w * wcol[j + 3];
        }
        #pragma unroll
        for (int o = 16; o; o >>= 1) s += __shfl_xor_sync(0xffffffff, s, o);
        if (lane == 0) g_Tbias[row] = s + wbias;
    }
}

// gold spans: warp per span, lane-parallel dedup, -s[gold] (bf16 dot)
__global__ __launch_bounds__(256) void k_gold(const int* __restrict__ gold,
                                              const int* __restrict__ seq_len) {
    __shared__ float wsum[8];
    int wid = threadIdx.x >> 5, lane = threadIdx.x & 31;
    int g = blockIdx.x * 8 + wid;
    float val = 0.f;
    int gb = gold[3 * g], gl = gold[3 * g + 1], gr = gold[3 * g + 2];
    if (gr > gl && gr <= seq_len[gb]) {
        int key = (gb << 16) | (gl << 8) | gr;
        bool dup = false;
        for (int p = lane; p < g; p += 32) {
            int k2 = (gold[3 * p] << 16) | (gold[3 * p + 1] << 8) | gold[3 * p + 2];
            if (k2 == key) dup = true;
        }
        dup = __any_sync(0xffffffff, dup);
        if (!dup) {
            const __nv_bfloat16* tr = g_Tb + (size_t)(gb * Ln + gl) * Dn;
            const __nv_bfloat16* rr = g_reprs_b + (size_t)(gb * Ln + gr) * Dn;
            float s = 0.f;
            for (int j = lane * 8; j < 1024; j += 256) {
                uint4 tv = *reinterpret_cast<const uint4*>(tr + j);
                uint4 rv = *reinterpret_cast<const uint4*>(rr + j);
                float2 t0 = upk2(tv.x), t1 = upk2(tv.y), t2 = upk2(tv.z), t3 = upk2(tv.w);
                float2 r0 = upk2(rv.x), r1 = upk2(rv.y), r2 = upk2(rv.z), r3 = upk2(rv.w);
                s += t0.x * r0.x + t0.y * r0.y + t1.x * r1.x + t1.y * r1.y
                   + t2.x * r2.x + t2.y * r2.y + t3.x * r3.x + t3.y * r3.y;
            }
            #pragma unroll
            for (int o = 16; o; o >>= 1) s += __shfl_xor_sync(0xffffffff, s, o);
            if (lane == 0) val = -(s + g_Tbias[gb * Ln + gl]);
        }
    }
    if (lane == 0) wsum[wid] = val;
    __syncthreads();
    if (threadIdx.x == 0) {
        float t = 0.f;
        #pragma unroll
        for (int i = 0; i < 8; i++) t += wsum[i];
        g_gold_part[blockIdx.x] = t;
    }
}

// gold_repr (bf16) = concat(end-start, maxpool word_repr[start:end))
__global__ __launch_bounds__(256) void k_gold_repr(const float* __restrict__ reprs,
                                                   const int* __restrict__ span_start,
                                                   const int* __restrict__ span_end) {
    int row = blockIdx.x, tid = threadIdx.x;
    int b = row >> 6;
    int s = span_start[row], e = span_end[row];
    const float4* rs = reinterpret_cast<const float4*>(reprs + ((size_t)b * Ln + s) * Dn);
    const float4* re = reinterpret_cast<const float4*>(reprs + ((size_t)b * Ln + e) * Dn);
    float4 a = re[tid], c = rs[tid];
    uint2 o;
    o.x = pk2(a.x - c.x, a.y - c.y);
    o.y = pk2(a.z - c.z, a.w - c.w);
    *reinterpret_cast<uint2*>(g_goldb + (size_t)row * 2048 + tid * 4) = o;

    float m0 = NEGV, m1 = NEGV, m2 = NEGV, m3 = NEGV;
    const __nv_bfloat16* wb = g_word_b + (size_t)b * Wn * Dn + tid * 4;
    int ee = min(e, Wn);
    for (int w = s; w < ee; w++) {
        uint2 v = *reinterpret_cast<const uint2*>(wb + (size_t)w * Dn);
        float2 f0 = upk2(v.x), f1 = upk2(v.y);
        m0 = fmaxf(m0, f0.x); m1 = fmaxf(m1, f0.y);
        m2 = fmaxf(m2, f1.x); m3 = fmaxf(m3, f1.y);
    }
    uint2 p; p.x = pk2(m0, m1); p.y = pk2(m2, m3);
    *reinterpret_cast<uint2*>(g_goldb + (size_t)row * 2048 + 1024 + tid * 4) = p;
}

// reduce h1 partials + bias, relu(LayerNorm)
__global__ __launch_bounds__(256) void k_ln(const float* __restrict__ bp1,
                                            const float* __restrict__ gamma,
                                            const float* __restrict__ beta) {
    __shared__ float red[256];
    int row = blockIdx.x, tid = threadIdx.x;
    float x = bp1[tid];
    #pragma unroll
    for (int p = 0; p < 8; p++) x += g_h1p[((size_t)p * 512 + row) * 256 + tid];
    red[tid] = x; __syncthreads();
    for (int s = 128; s > 0; s >>= 1) { if (tid < s) red[tid] += red[tid + s]; __syncthreads(); }
    float mean = red[0] * (1.0f / En); __syncthreads();
    float d = x - mean;
    red[tid] = d * d; __syncthreads();
    for (int s = 128; s > 0; s >>= 1) { if (tid < s) red[tid] += red[tid + s]; __syncthreads(); }
    float var = red[0] * (1.0f / En);
    float y = d * rsqrtf(var + 1e-5f) * gamma[tid] + beta[tid];
    g_h[(size_t)row * En + tid] = fmaxf(y, 0.f);
}

// fused tail: h2 = h@Wp2^T+b2, logits = h2@Lab^T, log-softmax CE
__global__ __launch_bounds__(256) void k_tail(const float* __restrict__ Wp2,
                                              const float* __restrict__ bp2,
                                              const float* __restrict__ lab,
                                              const int* __restrict__ chart,
                                              const int* __restrict__ action_len) {
    __shared__ float h[8][256];
    __shared__ float h2[8][256];
    __shared__ float lg[8][128];
    __shared__ float red[128];
    int tid = threadIdx.x;
    int r0 = blockIdx.x * 8;
    #pragma unroll
    for (int r = 0; r < 8; r++) h[r][tid] = g_h[(size_t)(r0 + r) * 256 + tid];
    __syncthreads();
    {
        float acc[8] = {0, 0, 0, 0, 0, 0, 0, 0};
        const float4* wr = reinterpret_cast<const float4*>(Wp2 + (size_t)tid * 256);
        for (int k = 0; k < 64; k++) {
            float4 w = wr[k];
            #pragma unroll
            for (int r = 0; r < 8; r++)
                acc[r] += w.x * h[r][4 * k] + w.y * h[r][4 * k + 1]
                        + w.z * h[r][4 * k + 2] + w.w * h[r][4 * k + 3];
        }
        float bb = bp2[tid];
        #pragma unroll
        for (int r = 0; r < 8; r++) h2[r][tid] = acc[r] + bb;
    }
    __syncthreads();
    if (tid < 128) {
        float acc[8] = {0, 0, 0, 0, 0, 0, 0, 0};
        const float4* lr = reinterpret_cast<const float4*>(lab + (size_t)tid * 256);
        for (int k = 0; k < 64; k++) {
            float4 w = lr[k];
            #pragma unroll
            for (int r = 0; r < 8; r++)
                acc[r] += w.x * h2[r][4 * k] + w.y * h2[r][4 * k + 1]
                        + w.z * h2[r][4 * k + 2] + w.w * h2[r][4 * k + 3];
        }
        #pragma unroll
        for (int r = 0; r < 8; r++) lg[r][tid] = acc[r];
    }
    __syncthreads();
    for (int r = 0; r < 8; r++) {
        if (tid < 128) red[tid] = lg[r][tid];
        __syncthreads();
        for (int s = 64; s > 0; s >>= 1) { if (tid < s) red[tid] = fmaxf(red[tid], red[tid + s]); __syncthreads(); }
        float mx = red[0]; __syncthreads();
        if (tid < 128) red[tid] = expf(lg[r][tid] - mx);
        __syncthreads();
        for (int s = 64; s > 0; s >>= 1) { if (tid < s) red[tid] += red[tid + s]; __syncthreads(); }
        if (tid == 0) {
            int row = r0 + r;
            int b = row >> 6, a = row & 63;
            float lse = logf(red[0]);
            float ce = -(lg[r][chart[row]] - mx - lse);
            g_ce_part[row] = (a < action_len[b]) ? ce : 0.f;
        }
        __syncthreads();
    }
}

// final deterministic reduction
__global__ __launch_bounds__(512) void k_final(const int* __restrict__ action_len,
                                               float* __restrict__ out) {
    __shared__ float red[512];
    int tid = threadIdx.x;
    float num = (tid < 80 ? g_span_sum[tid] : 0.f) + (tid < 256 ? g_gold_part[tid] : 0.f);
    red[tid] = num; __syncthreads();
    for (int s = 256; s > 0; s >>= 1) { if (tid < s) red[tid] += red[tid + s]; __syncthreads(); }
    float span_num = red[0]; __syncthreads();

    red[tid] = (tid < 80 ? g_span_cnt2[tid] : 0.f); __syncthreads();
    for (int s = 256; s > 0; s >>= 1) { if (tid < s) red[tid] += red[tid + s]; __syncthreads(); }
    float span_cnt = red[0]; __syncthreads();

    red[tid] = g_ce_part[tid]; __syncthreads();
    for (int s = 256; s > 0; s >>= 1) { if (tid < s) red[tid] += red[tid + s]; __syncthreads(); }
    float ce_sum = red[0];

    if (tid == 0) {
        int lc = 0;
        for (int b = 0; b < Bn; b++) lc += action_len[b];
        out[0] = span_num / span_cnt + ce_sum / (float)lc;
    }
}

// ===================== launch =====================
extern "C" void kernel_launch(void* const* d_in, const int* in_sizes, int n_in,
                              void* d_out, int out_size) {
    const float* reprs      = (const float*)d_in[0];
    const float* word_repr  = (const float*)d_in[1];
    const int*   seq_len    = (const int*)d_in[2];
    const int*   gold_span  = (const int*)d_in[3];
    const int*   span_start = (const int*)d_in[4];
    const int*   span_end   = (const int*)d_in[5];
    const int*   chart      = (const int*)d_in[6];
    const int*   action_len = (const int*)d_in[7];
    const float* Wb         = (const float*)d_in[8];
    const float* Wp1        = (const float*)d_in[9];
    const float* bp1        = (const float*)d_in[10];
    const float* gamma      = (const float*)d_in[11];
    const float* beta       = (const float*)d_in[12];
    const float* Wp2        = (const float*)d_in[13];
    const float* bp2        = (const float*)d_in[14];
    const float* lab        = (const float*)d_in[15];
    float* out = (float*)d_out;

    // conversions + W transpose + bias column
    k_convert<<<2300, 256>>>(reprs, word_repr, Wp1);
    k_wt<<<dim3(16, 16), 256>>>(Wb);
    k_bias_col<<<64, 256>>>(reprs, Wb);

    // tensor-core (HMMA) GEMMs
    k_gemm1_mma<<<dim3(8, 16), 256>>>(Wb);             // T bf16 (bias row fused)
    k_span_mma<<<dim3(10, 8), 256>>>(seq_len);         // 64x64 tiles, fused softplus
    k_gold<<<256, 256>>>(gold_span, seq_len);          // gold dots (bf16)

    // label path
    k_gold_repr<<<Bn * An, 256>>>(reprs, span_start, span_end);
    k_h1_mma<<<dim3(2, 4, 8), 256>>>();                // split-K=8
    k_ln<<<512, 256>>>(bp1, gamma, beta);
    k_tail<<<64, 256>>>(Wp2, bp2, lab, chart, action_len);

    k_final<<<1, 512>>>(action_len, out);
}

// round 8
// speedup vs baseline: 9.3431x; 1.0658x over previous
// R8: 3-stage XOR-swizzled cp.async pipeline (depth-2 prefetch) for all HMMA kernels;
// prelude kernels merged. Same numerics as R7 (rel_err 6.4e-6).
#include <cuda_runtime.h>
#include <cuda_bf16.h>
#include <math.h>
#include <stdint.h>

// Problem constants
#define Bn   8
#define Ln   256
#define Dn   1024
#define An   64
#define Vn   128
#define En   256
#define Gn   2048
#define Wn   255
#define NEGV (-1000.0f)

// bf16 pack/unpack
__device__ __forceinline__ uint32_t pk2(float a, float b) {
    __nv_bfloat162 h; h.x = __float2bfloat16(a); h.y = __float2bfloat16(b);
    return *reinterpret_cast<uint32_t*>(&h);
}
__device__ __forceinline__ float2 upk2(uint32_t u) {
    __nv_bfloat162 h = *reinterpret_cast<__nv_bfloat162*>(&u);
    return __bfloat1622float2(h);
}
__device__ __forceinline__ uint32_t sm_u32(const void* p) {
    uint32_t a;
    asm("{ .reg .u64 t; cvta.to.shared.u64 t, %1; cvt.u32.u64 %0, t; }" : "=r"(a) : "l"(p));
    return a;
}

// warp mma: D(16x8,f32) += A(16x16,bf16,row) * B(16x8,bf16,col)
__device__ __forceinline__ void mma16816(float d[4], uint32_t a0, uint32_t a1,
                                         uint32_t a2, uint32_t a3,
                                         uint32_t b0, uint32_t b1) {
    asm volatile(
        "mma.sync.aligned.m16n8k16.row.col.f32.bf16.bf16.f32 "
        "{%0,%1,%2,%3}, {%4,%5,%6,%7}, {%8,%9}, {%0,%1,%2,%3};\n"
        : "+f"(d[0]), "+f"(d[1]), "+f"(d[2]), "+f"(d[3])
        : "r"(a0), "r"(a1), "r"(a2), "r"(a3), "r"(b0), "r"(b1));
}
__device__ __forceinline__ void ldsm_x4(uint32_t r[4], uint32_t addr) {
    asm volatile("ldmatrix.sync.aligned.m8n8.x4.shared.b16 {%0,%1,%2,%3}, [%4];\n"
                 : "=r"(r[0]), "=r"(r[1]), "=r"(r[2]), "=r"(r[3]) : "r"(addr));
}
__device__ __forceinline__ void cp16(uint32_t s_dst, const void* g_src) {
    asm volatile("cp.async.cg.shared.global [%0], [%1], 16;\n" :: "r"(s_dst), "l"(g_src));
}
#define CP_COMMIT() asm volatile("cp.async.commit_group;\n" ::: "memory")
#define CP_WAIT2()  asm volatile("cp.async.wait_group 2;\n" ::: "memory")

// ===================== device scratch =====================
__device__ __align__(16) __nv_bfloat16 g_reprs_b[Bn * Ln * Dn];   // 4 MB
__device__ __align__(16) __nv_bfloat16 g_word_b[Bn * Wn * Dn];    // ~4 MB
__device__ __align__(16) __nv_bfloat16 g_Wp1b[En * 2 * Dn];       // 1 MB
__device__ __align__(16) __nv_bfloat16 g_Wt[Dn * Dn];             // W^T bf16, 2 MB
__device__ __align__(16) __nv_bfloat16 g_Tb[Bn * Ln * Dn];        // T bf16, 4 MB
__device__ float g_Tbias[Bn * Ln];                                 // T[:,1024] fp32
__device__ __align__(16) __nv_bfloat16 g_goldb[Bn * An * 2 * Dn]; // 2 MB
__device__ float g_h1p[8 * 512 * 256];                             // h1 split-K partials
__device__ float g_h[512 * 256];
__device__ float g_span_sum[80];
__device__ float g_span_cnt2[80];
__device__ float g_gold_part[256];
__device__ float g_ce_part[512];

// ===================== merged prelude =====================
// blocks [0,2300): fp32->bf16 conversion of reprs/word_repr/Wp1
// blocks [2300,2556): W^T bf16 64x64 transpose tiles
// blocks [2556,2620): T bias column dot products
#define N_REPRS (Bn * Ln * Dn)        // 2097152
#define N_WORD  (Bn * Wn * Dn)        // 2088960
#define N_WP1   (En * 2 * Dn)         // 524288
#define CV_BLOCKS 2300
#define WT_BLOCKS 256
__global__ __launch_bounds__(256) void k_prelude(const float* __restrict__ reprs,
                                                 const float* __restrict__ word,
                                                 const float* __restrict__ wp1,
                                                 const float* __restrict__ Wb) {
    __shared__ float sh[64 * 65];
    int bx = blockIdx.x;
    if (bx < CV_BLOCKS) {
        size_t i = ((size_t)bx * 256 + threadIdx.x) * 8;
        const float* src; __nv_bfloat16* dst;
        if (i < N_REPRS) { src = reprs + i; dst = g_reprs_b + i; }
        else if (i < (size_t)N_REPRS + N_WORD) { size_t j = i - N_REPRS; src = word + j; dst = g_word_b + j; }
        else { size_t j = i - N_REPRS - N_WORD; src = wp1 + j; dst = g_Wp1b + j; }
        float4 a = *reinterpret_cast<const float4*>(src);
        float4 b = *reinterpret_cast<const float4*>(src + 4);
        uint4 o;
        o.x = pk2(a.x, a.y); o.y = pk2(a.z, a.w);
        o.z = pk2(b.x, b.y); o.w = pk2(b.z, b.w);
        *reinterpret_cast<uint4*>(dst) = o;
    } else if (bx < CV_BLOCKS + WT_BLOCKS) {
        int idx = bx - CV_BLOCKS;
        int n0 = (idx & 15) * 64, k0 = (idx >> 4) * 64;
        int r = threadIdx.x >> 2, cq = (threadIdx.x & 3) * 16;
        #pragma unroll
        for (int i = 0; i < 16; i++)
            sh[r * 65 + cq + i] = Wb[(size_t)(k0 + r) * 1025 + n0 + cq + i];
        __syncthreads();
        uint32_t pk[8];
        #pragma unroll
        for (int j = 0; j < 8; j++)
            pk[j] = pk2(sh[(cq + 2 * j) * 65 + r], sh[(cq + 2 * j + 1) * 65 + r]);
        __nv_bfloat16* dst = g_Wt + (size_t)(n0 + r) * 1024 + k0 + cq;
        *reinterpret_cast<uint4*>(dst)     = make_uint4(pk[0], pk[1], pk[2], pk[3]);
        *reinterpret_cast<uint4*>(dst + 8) = make_uint4(pk[4], pk[5], pk[6], pk[7]);
    } else {
        int idx = bx - CV_BLOCKS - WT_BLOCKS;
        float* wcol = sh;
        for (int i = threadIdx.x; i < 1024; i += 256) wcol[i] = Wb[(size_t)i * 1025 + 1024];
        __syncthreads();
        int wid = threadIdx.x >> 5, lane = threadIdx.x & 31;
        float wbias = Wb[(size_t)1024 * 1025 + 1024];
        #pragma unroll
        for (int rr = 0; rr < 4; rr++) {
            int row = idx * 32 + wid * 4 + rr;
            const float* ar = reprs + (size_t)row * 1024;
            float s = 0.f;
            for (int j = lane * 4; j < 1024; j += 128) {
                float4 a = *reinterpret_cast<const float4*>(ar + j);
                s += a.x * wcol[j] + a.y * wcol[j + 1] + a.z * wcol[j + 2] + a.w * wcol[j + 3];
            }
            #pragma unroll
            for (int o = 16; o; o >>= 1) s += __shfl_xor_sync(0xffffffff, s, o);
            if (lane == 0) g_Tbias[row] = s + wbias;
        }
    }
}

// ===================== HMMA NT mainloop: 3-stage, swizzled 64B rows =====================
// SMEM tile: R rows x 32 bf16 (64 B). Element (r,k): seg=k>>3 stored at
// seg' = seg ^ ((r>>1)&3). 3 stages; depth-2 prefetch; uniform commit/wait_group 2.
// Warp bases are multiples of 16 rows -> swizzle XOR is a per-lane constant.

template<int BM, int BN, int MI, int NI>
__device__ __forceinline__ void mma_nt_loop(
    const __nv_bfloat16* __restrict__ Ag, int lda, int m0,
    const __nv_bfloat16* __restrict__ Bg, int ldb, int n0,
    int kbeg, int kend, float acc[MI][NI][4],
    __nv_bfloat16* As, __nv_bfloat16* Bs)   // [3][BM*32], [3][BN*32]
{
    constexpr int WC = BN / (8 * NI);
    int tid = threadIdx.x;
    int lane = tid & 31, warp = tid >> 5;
    int wm = warp / WC, wn = warp % WC;

    // cp.async addressing: 256 threads cover 64 rows x 4 segs per iteration
    int ldr = tid >> 2, seg = tid & 3;
    int sw = seg ^ ((ldr >> 1) & 3);
    const __nv_bfloat16* Arow = Ag + (size_t)(m0 + ldr) * lda + seg * 8;
    const __nv_bfloat16* Brow = Bg + (size_t)(n0 + ldr) * ldb + seg * 8;
    uint32_t sa_st = sm_u32(As) + ldr * 64 + sw * 16;
    uint32_t sb_st = sm_u32(Bs) + ldr * 64 + sw * 16;
    constexpr int AIT = BM / 64, BIT = BN / 64;
    constexpr uint32_t stA = (uint32_t)BM * 64;   // bytes per stage
    constexpr uint32_t stB = (uint32_t)BN * 64;

    // ldmatrix lane bases (stage 0)
    int a_r = lane & 15;
    uint32_t a_base = sm_u32(As) + (uint32_t)(wm * MI * 16 + a_r) * 64;
    int xa = (a_r >> 1) & 3;
    int a_hi = lane >> 4;              // k half 0/1
    int b_r = (lane & 7) + 8 * (lane >> 4);
    uint32_t b_base = sm_u32(Bs) + (uint32_t)(wn * NI * 8 + b_r) * 64;
    int xb = (b_r >> 1) & 3;
    int b_hi = (lane >> 3) & 1;

    int nc = (kend - kbeg) >> 5;
    // preload chunks 0..2 into stages 0..2 (commit even if past end: empty groups)
    #pragma unroll
    for (int p = 0; p < 3; p++) {
        if (p < nc) {
            int kc = kbeg + p * 32;
            #pragma unroll
            for (int it = 0; it < AIT; it++)
                cp16(sa_st + p * stA + it * 4096, Arow + (size_t)it * 64 * lda + kc);
            #pragma unroll
            for (int it = 0; it < BIT; it++)
                cp16(sb_st + p * stB + it * 4096, Brow + (size_t)it * 64 * ldb + kc);
        }
        CP_COMMIT();
    }

    for (int c = 0; c < nc; c++) {
        CP_WAIT2();                // group c complete (2 newer groups may be pending)
        __syncthreads();
        int st = c % 3;
        uint32_t a0 = a_base + st * stA;
        uint32_t b0 = b_base + st * stB;
        #pragma unroll
        for (int kk = 0; kk < 2; kk++) {
            uint32_t af[MI][4], bfr[NI][2];
            #pragma unroll
            for (int mi = 0; mi < MI; mi++)
                ldsm_x4(af[mi], a0 + mi * 1024 + ((((kk * 2 + a_hi)) ^ xa) << 4));
            #pragma unroll
            for (int nj = 0; nj < NI / 2; nj++) {
                uint32_t br[4];
                ldsm_x4(br, b0 + nj * 1024 + ((((kk * 2 + b_hi)) ^ xb) << 4));
                bfr[2 * nj][0] = br[0]; bfr[2 * nj][1] = br[1];
                bfr[2 * nj + 1][0] = br[2]; bfr[2 * nj + 1][1] = br[3];
            }
            #pragma unroll
            for (int mi = 0; mi < MI; mi++)
                #pragma unroll
                for (int ni = 0; ni < NI; ni++)
                    mma16816(acc[mi][ni], af[mi][0], af[mi][1], af[mi][2], af[mi][3],
                             bfr[ni][0], bfr[ni][1]);
        }
        __syncthreads();           // all warps done reading stage st
        if (c + 3 < nc) {          // refill freed stage with chunk c+3
            int kc = kbeg + (c + 3) * 32;
            #pragma unroll
            for (int it = 0; it < AIT; it++)
                cp16(sa_st + st * stA + it * 4096, Arow + (size_t)it * 64 * lda + kc);
            #pragma unroll
            for (int it = 0; it < BIT; it++)
                cp16(sb_st + st * stB + it * 4096, Brow + (size_t)it * 64 * ldb + kc);
        }
        CP_COMMIT();
    }
}

// ---- GEMM1: T_bf16 = reprs_b @ Wt^T (+ bias row), M=2048, N=1024, K=1024 ----
__global__ __launch_bounds__(256) void k_gemm1_mma(const float* __restrict__ Wb) {
    __shared__ __align__(16) __nv_bfloat16 As[3 * 128 * 32];
    __shared__ __align__(16) __nv_bfloat16 Bs[3 * 128 * 32];
    float acc[4][4][4] = {};
    int m0 = blockIdx.y * 128, n0 = blockIdx.x * 128;
    mma_nt_loop<128, 128, 4, 4>(g_reprs_b, 1024, m0, g_Wt, 1024, n0, 0, 1024, acc, As, Bs);
    int lane = threadIdx.x & 31, warp = threadIdx.x >> 5;
    int wm = warp >> 2, wn = warp & 3, g = lane >> 2, tg = lane & 3;
    const float* brow = Wb + (size_t)1024 * 1025;
    #pragma unroll
    for (int mi = 0; mi < 4; mi++) {
        int m = m0 + wm * 64 + mi * 16 + g;
        #pragma unroll
        for (int ni = 0; ni < 4; ni++) {
            int n = n0 + wn * 32 + ni * 8 + 2 * tg;
            float b0 = brow[n], b1 = brow[n + 1];
            *reinterpret_cast<uint32_t*>(g_Tb + (size_t)m * 1024 + n) =
                pk2(acc[mi][ni][0] + b0, acc[mi][ni][1] + b1);
            *reinterpret_cast<uint32_t*>(g_Tb + (size_t)(m + 8) * 1024 + n) =
                pk2(acc[mi][ni][2] + b0, acc[mi][ni][3] + b1);
        }
    }
}

// ---- span GEMM 64x64 tiles + fused masked softplus epilogue ----
// grid (10, 8): upper-triangle tile list, b = blockIdx.y
__constant__ int c_xt[10] = {0, 0, 0, 0, 1, 1, 1, 2, 2, 3};
__constant__ int c_yt[10] = {0, 1, 2, 3, 1, 2, 3, 2, 3, 3};
__global__ __launch_bounds__(256) void k_span_mma(const int* __restrict__ seq_len) {
    __shared__ __align__(16) __nv_bfloat16 As[3 * 64 * 32];
    __shared__ __align__(16) __nv_bfloat16 Bs[3 * 64 * 32];
    __shared__ float red[256];
    int t = blockIdx.x, b = blockIdx.y;
    int x0 = c_xt[t] * 64, y0 = c_yt[t] * 64;
    int slot = b * 10 + t;
    int sl = seq_len[b];
    int tid = threadIdx.x;
    if (y0 > sl) {
        if (tid == 0) { g_span_sum[slot] = 0.f; g_span_cnt2[slot] = 0.f; }
        return;
    }
    // 8 warps 2x4, warp tile 32x16: MI=2, NI=2
    float acc[2][2][4] = {};
    mma_nt_loop<64, 64, 2, 2>(g_Tb + (size_t)b * Ln * Dn, 1024, x0,
                              g_reprs_b + (size_t)b * Ln * Dn, 1024, y0, 0, 1024, acc, As, Bs);
    int lane = tid & 31, warp = tid >> 5;
    int wm = warp >> 2, wn = warp & 3, g = lane >> 2, tg = lane & 3;
    float lsum = 0.f, lcnt = 0.f;
    #pragma unroll
    for (int mi = 0; mi < 2; mi++) {
        int xA = x0 + wm * 32 + mi * 16 + g;
        int xB = xA + 8;
        float tbA = g_Tbias[b * Ln + xA];
        float tbB = g_Tbias[b * Ln + xB];
        #pragma unroll
        for (int ni = 0; ni < 2; ni++) {
            int y = y0 + wn * 16 + ni * 8 + 2 * tg;
            #pragma unroll
            for (int e = 0; e < 4; e++) {
                int yy = y + (e & 1);
                int xx = (e < 2) ? xA : xB;
                float tb = (e < 2) ? tbA : tbB;
                if (yy > xx && yy <= sl) {
                    float s = acc[mi][ni][e] + tb;
                    lsum += fmaxf(s, 0.f) + log1pf(expf(-fabsf(s)));
                    lcnt += 1.f;
                }
            }
        }
    }
    red[tid] = lsum; __syncthreads();
    for (int s = 128; s > 0; s >>= 1) { if (tid < s) red[tid] += red[tid + s]; __syncthreads(); }
    float tot = red[0]; __syncthreads();
    red[tid] = lcnt; __syncthreads();
    for (int s = 128; s > 0; s >>= 1) { if (tid < s) red[tid] += red[tid + s]; __syncthreads(); }
    if (tid == 0) { g_span_sum[slot] = tot; g_span_cnt2[slot] = red[0]; }
}

// ---- h1 split-K=8: partials[ks] = gold_b @ Wp1_b^T over K slice ----
__global__ __launch_bounds__(256) void k_h1_mma() {
    __shared__ __align__(16) __nv_bfloat16 As[3 * 128 * 32];
    __shared__ __align__(16) __nv_bfloat16 Bs[3 * 128 * 32];
    float acc[4][4][4] = {};
    int n0 = blockIdx.x * 128, m0 = blockIdx.y * 128, ks = blockIdx.z;
    mma_nt_loop<128, 128, 4, 4>(g_goldb, 2048, m0, g_Wp1b, 2048, n0,
                                ks * 256, ks * 256 + 256, acc, As, Bs);
    int lane = threadIdx.x & 31, warp = threadIdx.x >> 5;
    int wm = warp >> 2, wn = warp & 3, g = lane >> 2, tg = lane & 3;
    float* dst = g_h1p + (size_t)ks * 512 * 256;
    #pragma unroll
    for (int mi = 0; mi < 4; mi++) {
        int m = m0 + wm * 64 + mi * 16 + g;
        #pragma unroll
        for (int ni = 0; ni < 4; ni++) {
            int n = n0 + wn * 32 + ni * 8 + 2 * tg;
            *reinterpret_cast<float2*>(dst + (size_t)m * 256 + n) =
                make_float2(acc[mi][ni][0], acc[mi][ni][1]);
            *reinterpret_cast<float2*>(dst + (size_t)(m + 8) * 256 + n) =
                make_float2(acc[mi][ni][2], acc[mi][ni][3]);
        }
    }
}

// ===================== non-tensor kernels =====================

// gold spans: warp per span, lane-parallel dedup, -s[gold] (bf16 dot)
__global__ __launch_bounds__(256) void k_gold(const int* __restrict__ gold,
                                              const int* __restrict__ seq_len) {
    __shared__ float wsum[8];
    int wid = threadIdx.x >> 5, lane = threadIdx.x & 31;
    int g = blockIdx.x * 8 + wid;
    float val = 0.f;
    int gb = gold[3 * g], gl = gold[3 * g + 1], gr = gold[3 * g + 2];
    if (gr > gl && gr <= seq_len[gb]) {
        int key = (gb << 16) | (gl << 8) | gr;
        bool dup = false;
        for (int p = lane; p < g; p += 32) {
            int k2 = (gold[3 * p] << 16) | (gold[3 * p + 1] << 8) | gold[3 * p + 2];
            if (k2 == key) dup = true;
        }
        dup = __any_sync(0xffffffff, dup);
        if (!dup) {
            const __nv_bfloat16* tr = g_Tb + (size_t)(gb * Ln + gl) * Dn;
            const __nv_bfloat16* rr = g_reprs_b + (size_t)(gb * Ln + gr) * Dn;
            float s = 0.f;
            for (int j = lane * 8; j < 1024; j += 256) {
                uint4 tv = *reinterpret_cast<const uint4*>(tr + j);
                uint4 rv = *reinterpret_cast<const uint4*>(rr + j);
                float2 t0 = upk2(tv.x), t1 = upk2(tv.y), t2 = upk2(tv.z), t3 = upk2(tv.w);
                float2 r0 = upk2(rv.x), r1 = upk2(rv.y), r2 = upk2(rv.z), r3 = upk2(rv.w);
                s += t0.x * r0.x + t0.y * r0.y + t1.x * r1.x + t1.y * r1.y
                   + t2.x * r2.x + t2.y * r2.y + t3.x * r3.x + t3.y * r3.y;
            }
            #pragma unroll
            for (int o = 16; o; o >>= 1) s += __shfl_xor_sync(0xffffffff, s, o);
            if (lane == 0) val = -(s + g_Tbias[gb * Ln + gl]);
        }
    }
    if (lane == 0) wsum[wid] = val;
    __syncthreads();
    if (threadIdx.x == 0) {
        float t = 0.f;
        #pragma unroll
        for (int i = 0; i < 8; i++) t += wsum[i];
        g_gold_part[blockIdx.x] = t;
    }
}

// gold_repr (bf16) = concat(end-start, maxpool word_repr[start:end))
__global__ __launch_bounds__(256) void k_gold_repr(const float* __restrict__ reprs,
                                                   const int* __restrict__ span_start,
                                                   const int* __restrict__ span_end) {
    int row = blockIdx.x, tid = threadIdx.x;
    int b = row >> 6;
    int s = span_start[row], e = span_end[row];
    const float4* rs = reinterpret_cast<const float4*>(reprs + ((size_t)b * Ln + s) * Dn);
    const float4* re = reinterpret_cast<const float4*>(reprs + ((size_t)b * Ln + e) * Dn);
    float4 a = re[tid], c = rs[tid];
    uint2 o;
    o.x = pk2(a.x - c.x, a.y - c.y);
    o.y = pk2(a.z - c.z, a.w - c.w);
    *reinterpret_cast<uint2*>(g_goldb + (size_t)row * 2048 + tid * 4) = o;

    float m0 = NEGV, m1 = NEGV, m2 = NEGV, m3 = NEGV;
    const __nv_bfloat16* wb = g_word_b + (size_t)b * Wn * Dn + tid * 4;
    int ee = min(e, Wn);
    for (int w = s; w < ee; w++) {
        uint2 v = *reinterpret_cast<const uint2*>(wb + (size_t)w * Dn);
        float2 f0 = upk2(v.x), f1 = upk2(v.y);
        m0 = fmaxf(m0, f0.x); m1 = fmaxf(m1, f0.y);
        m2 = fmaxf(m2, f1.x); m3 = fmaxf(m3, f1.y);
    }
    uint2 p; p.x = pk2(m0, m1); p.y = pk2(m2, m3);
    *reinterpret_cast<uint2*>(g_goldb + (size_t)row * 2048 + 1024 + tid * 4) = p;
}

// reduce h1 partials + bias, relu(LayerNorm)
__global__ __launch_bounds__(256) void k_ln(const float* __restrict__ bp1,
                                            const float* __restrict__ gamma,
                                            const float* __restrict__ beta) {
    __shared__ float red[256];
    int row = blockIdx.x, tid = threadIdx.x;
    float x = bp1[tid];
    #pragma unroll
    for (int p = 0; p < 8; p++) x += g_h1p[((size_t)p * 512 + row) * 256 + tid];
    red[tid] = x; __syncthreads();
    for (int s = 128; s > 0; s >>= 1) { if (tid < s) red[tid] += red[tid + s]; __syncthreads(); }
    float mean = red[0] * (1.0f / En); __syncthreads();
    float d = x - mean;
    red[tid] = d * d; __syncthreads();
    for (int s = 128; s > 0; s >>= 1) { if (tid < s) red[tid] += red[tid + s]; __syncthreads(); }
    float var = red[0] * (1.0f / En);
    float y = d * rsqrtf(var + 1e-5f) * gamma[tid] + beta[tid];
    g_h[(size_t)row * En + tid] = fmaxf(y, 0.f);
}

// fused tail: h2 = h@Wp2^T+b2, logits = h2@Lab^T, log-softmax CE
__global__ __launch_bounds__(256) void k_tail(const float* __restrict__ Wp2,
                                              const float* __restrict__ bp2,
                                              const float* __restrict__ lab,
                                              const int* __restrict__ chart,
                                              const int* __restrict__ action_len) {
    __shared__ float h[8][256];
    __shared__ float h2[8][256];
    __shared__ float lg[8][128];
    __shared__ float red[128];
    int tid = threadIdx.x;
    int r0 = blockIdx.x * 8;
    #pragma unroll
    for (int r = 0; r < 8; r++) h[r][tid] = g_h[(size_t)(r0 + r) * 256 + tid];
    __syncthreads();
    {
        float acc[8] = {0, 0, 0, 0, 0, 0, 0, 0};
        const float4* wr = reinterpret_cast<const float4*>(Wp2 + (size_t)tid * 256);
        for (int k = 0; k < 64; k++) {
            float4 w = wr[k];
            #pragma unroll
            for (int r = 0; r < 8; r++)
                acc[r] += w.x * h[r][4 * k] + w.y * h[r][4 * k + 1]
                        + w.z * h[r][4 * k + 2] + w.w * h[r][4 * k + 3];
        }
        float bb = bp2[tid];
        #pragma unroll
        for (int r = 0; r < 8; r++) h2[r][tid] = acc[r] + bb;
    }
    __syncthreads();
    if (tid < 128) {
        float acc[8] = {0, 0, 0, 0, 0, 0, 0, 0};
        const float4* lr = reinterpret_cast<const float4*>(lab + (size_t)tid * 256);
        for (int k = 0; k < 64; k++) {
            float4 w = lr[k];
            #pragma unroll
            for (int r = 0; r < 8; r++)
                acc[r] += w.x * h2[r][4 * k] + w.y * h2[r][4 * k + 1]
                        + w.z * h2[r][4 * k + 2] + w.w * h2[r][4 * k + 3];
        }
        #pragma unroll
        for (int r = 0; r < 8; r++) lg[r][tid] = acc[r];
    }
    __syncthreads();
    for (int r = 0; r < 8; r++) {
        if (tid < 128) red[tid] = lg[r][tid];
        __syncthreads();
        for (int s = 64; s > 0; s >>= 1) { if (tid < s) red[tid] = fmaxf(red[tid], red[tid + s]); __syncthreads(); }
        float mx = red[0]; __syncthreads();
        if (tid < 128) red[tid] = expf(lg[r][tid] - mx);
        __syncthreads();
        for (int s = 64; s > 0; s >>= 1) { if (tid < s) red[tid] += red[tid + s]; __syncthreads(); }
        if (tid == 0) {
            int row = r0 + r;
            int b = row >> 6, a = row & 63;
            float lse = logf(red[0]);
            float ce = -(lg[r][chart[row]] - mx - lse);
            g_ce_part[row] = (a < action_len[b]) ? ce : 0.f;
        }
        __syncthreads();
    }
}

// final deterministic reduction
__global__ __launch_bounds__(512) void k_final(const int* __restrict__ action_len,
                                               float* __restrict__ out) {
    __shared__ float red[512];
    int tid = threadIdx.x;
    float num = (tid < 80 ? g_span_sum[tid] : 0.f) + (tid < 256 ? g_gold_part[tid] : 0.f);
    red[tid] = num; __syncthreads();
    for (int s = 256; s > 0; s >>= 1) { if (tid < s) red[tid] += red[tid + s]; __syncthreads(); }
    float span_num = red[0]; __syncthreads();

    red[tid] = (tid < 80 ? g_span_cnt2[tid] : 0.f); __syncthreads();
    for (int s = 256; s > 0; s >>= 1) { if (tid < s) red[tid] += red[tid + s]; __syncthreads(); }
    float span_cnt = red[0]; __syncthreads();

    red[tid] = g_ce_part[tid]; __syncthreads();
    for (int s = 256; s > 0; s >>= 1) { if (tid < s) red[tid] += red[tid + s]; __syncthreads(); }
    float ce_sum = red[0];

    if (tid == 0) {
        int lc = 0;
        for (int b = 0; b < Bn; b++) lc += action_len[b];
        out[0] = span_num / span_cnt + ce_sum / (float)lc;
    }
}

// ===================== launch =====================
extern "C" void kernel_launch(void* const* d_in, const int* in_sizes, int n_in,
                              void* d_out, int out_size) {
    const float* reprs      = (const float*)d_in[0];
    const float* word_repr  = (const float*)d_in[1];
    const int*   seq_len    = (const int*)d_in[2];
    const int*   gold_span  = (const int*)d_in[3];
    const int*   span_start = (const int*)d_in[4];
    const int*   span_end   = (const int*)d_in[5];
    const int*   chart      = (const int*)d_in[6];
    const int*   action_len = (const int*)d_in[7];
    const float* Wb         = (const float*)d_in[8];
    const float* Wp1        = (const float*)d_in[9];
    const float* bp1        = (const float*)d_in[10];
    const float* gamma      = (const float*)d_in[11];
    const float* beta       = (const float*)d_in[12];
    const float* Wp2        = (const float*)d_in[13];
    const float* bp2        = (const float*)d_in[14];
    const float* lab        = (const float*)d_in[15];
    float* out = (float*)d_out;

    // merged prelude: conversions + W^T + bias column
    k_prelude<<<CV_BLOCKS + WT_BLOCKS + 64, 256>>>(reprs, word_repr, Wp1, Wb);

    // tensor-core (HMMA) GEMMs, 3-stage pipelines
    k_gemm1_mma<<<dim3(8, 16), 256>>>(Wb);             // T bf16 (bias row fused)
    k_span_mma<<<dim3(10, 8), 256>>>(seq_len);         // 64x64 tiles, fused softplus
    k_gold<<<256, 256>>>(gold_span, seq_len);          // gold dots (bf16)

    // label path
    k_gold_repr<<<Bn * An, 256>>>(reprs, span_start, span_end);
    k_h1_mma<<<dim3(2, 4, 8), 256>>>();                // split-K=8
    k_ln<<<512, 256>>>(bp1, gamma, beta);
    k_tail<<<64, 256>>>(Wp2, bp2, lab, chart, action_len);

    k_final<<<1, 512>>>(action_len, out);
}

// round 9
// speedup vs baseline: 10.0070x; 1.0711x over previous
// R9: S=5 cp.async pipeline (depth-4 prefetch, dyn smem for 128x128), smem-key gold dedup,
// LN fused into tail. Numerics ~R8 (rel_err ~6e-6).
#include <cuda_runtime.h>
#include <cuda_bf16.h>
#include <math.h>
#include <stdint.h>

// Problem constants
#define Bn   8
#define Ln   256
#define Dn   1024
#define An   64
#define Vn   128
#define En   256
#define Gn   2048
#define Wn   255
#define NEGV (-1000.0f)

// bf16 pack/unpack
__device__ __forceinline__ uint32_t pk2(float a, float b) {
    __nv_bfloat162 h; h.x = __float2bfloat16(a); h.y = __float2bfloat16(b);
    return *reinterpret_cast<uint32_t*>(&h);
}
__device__ __forceinline__ float2 upk2(uint32_t u) {
    __nv_bfloat162 h = *reinterpret_cast<__nv_bfloat162*>(&u);
    return __bfloat1622float2(h);
}
__device__ __forceinline__ uint32_t sm_u32(const void* p) {
    uint32_t a;
    asm("{ .reg .u64 t; cvta.to.shared.u64 t, %1; cvt.u32.u64 %0, t; }" : "=r"(a) : "l"(p));
    return a;
}

// warp mma: D(16x8,f32) += A(16x16,bf16,row) * B(16x8,bf16,col)
__device__ __forceinline__ void mma16816(float d[4], uint32_t a0, uint32_t a1,
                                         uint32_t a2, uint32_t a3,
                                         uint32_t b0, uint32_t b1) {
    asm volatile(
        "mma.sync.aligned.m16n8k16.row.col.f32.bf16.bf16.f32 "
        "{%0,%1,%2,%3}, {%4,%5,%6,%7}, {%8,%9}, {%0,%1,%2,%3};\n"
        : "+f"(d[0]), "+f"(d[1]), "+f"(d[2]), "+f"(d[3])
        : "r"(a0), "r"(a1), "r"(a2), "r"(a3), "r"(b0), "r"(b1));
}
__device__ __forceinline__ void ldsm_x4(uint32_t r[4], uint32_t addr) {
    asm volatile("ldmatrix.sync.aligned.m8n8.x4.shared.b16 {%0,%1,%2,%3}, [%4];\n"
                 : "=r"(r[0]), "=r"(r[1]), "=r"(r[2]), "=r"(r[3]) : "r"(addr));
}
__device__ __forceinline__ void cp16(uint32_t s_dst, const void* g_src) {
    asm volatile("cp.async.cg.shared.global [%0], [%1], 16;\n" :: "r"(s_dst), "l"(g_src));
}
#define CP_COMMIT() asm volatile("cp.async.commit_group;\n" ::: "memory")

// ===================== device scratch =====================
__device__ __align__(16) __nv_bfloat16 g_reprs_b[Bn * Ln * Dn];   // 4 MB
__device__ __align__(16) __nv_bfloat16 g_word_b[Bn * Wn * Dn];    // ~4 MB
__device__ __align__(16) __nv_bfloat16 g_Wp1b[En * 2 * Dn];       // 1 MB
__device__ __align__(16) __nv_bfloat16 g_Wt[Dn * Dn];             // W^T bf16, 2 MB
__device__ __align__(16) __nv_bfloat16 g_Tb[Bn * Ln * Dn];        // T bf16, 4 MB
__device__ float g_Tbias[Bn * Ln];                                 // T[:,1024] fp32
__device__ __align__(16) __nv_bfloat16 g_goldb[Bn * An * 2 * Dn]; // 2 MB
__device__ float g_h1p[8 * 512 * 256];                             // h1 split-K partials
__device__ int   g_keys[Gn];                                       // packed gold keys
__device__ float g_span_sum[80];
__device__ float g_span_cnt2[80];
__device__ float g_gold_part[256];
__device__ float g_ce_part[512];

// ===================== merged prelude =====================
// blocks [0,2300): fp32->bf16 conversion of reprs/word_repr/Wp1
// blocks [2300,2556): W^T bf16 64x64 transpose tiles
// blocks [2556,2620): T bias column dot products
// blocks [2620,2628): packed gold keys
#define N_REPRS (Bn * Ln * Dn)        // 2097152
#define N_WORD  (Bn * Wn * Dn)        // 2088960
#define N_WP1   (En * 2 * Dn)         // 524288
#define CV_BLOCKS 2300
#define WT_BLOCKS 256
__global__ __launch_bounds__(256) void k_prelude(const float* __restrict__ reprs,
                                                 const float* __restrict__ word,
                                                 const float* __restrict__ wp1,
                                                 const float* __restrict__ Wb,
                                                 const int* __restrict__ gold) {
    __shared__ float sh[64 * 65];
    int bx = blockIdx.x;
    if (bx < CV_BLOCKS) {
        size_t i = ((size_t)bx * 256 + threadIdx.x) * 8;
        const float* src; __nv_bfloat16* dst;
        if (i < N_REPRS) { src = reprs + i; dst = g_reprs_b + i; }
        else if (i < (size_t)N_REPRS + N_WORD) { size_t j = i - N_REPRS; src = word + j; dst = g_word_b + j; }
        else { size_t j = i - N_REPRS - N_WORD; src = wp1 + j; dst = g_Wp1b + j; }
        float4 a = *reinterpret_cast<const float4*>(src);
        float4 b = *reinterpret_cast<const float4*>(src + 4);
        uint4 o;
        o.x = pk2(a.x, a.y); o.y = pk2(a.z, a.w);
        o.z = pk2(b.x, b.y); o.w = pk2(b.z, b.w);
        *reinterpret_cast<uint4*>(dst) = o;
    } else if (bx < CV_BLOCKS + WT_BLOCKS) {
        int idx = bx - CV_BLOCKS;
        int n0 = (idx & 15) * 64, k0 = (idx >> 4) * 64;
        int r = threadIdx.x >> 2, cq = (threadIdx.x & 3) * 16;
        #pragma unroll
        for (int i = 0; i < 16; i++)
            sh[r * 65 + cq + i] = Wb[(size_t)(k0 + r) * 1025 + n0 + cq + i];
        __syncthreads();
        uint32_t pk[8];
        #pragma unroll
        for (int j = 0; j < 8; j++)
            pk[j] = pk2(sh[(cq + 2 * j) * 65 + r], sh[(cq + 2 * j + 1) * 65 + r]);
        __nv_bfloat16* dst = g_Wt + (size_t)(n0 + r) * 1024 + k0 + cq;
        *reinterpret_cast<uint4*>(dst)     = make_uint4(pk[0], pk[1], pk[2], pk[3]);
        *reinterpret_cast<uint4*>(dst + 8) = make_uint4(pk[4], pk[5], pk[6], pk[7]);
    } else if (bx < CV_BLOCKS + WT_BLOCKS + 64) {
        int idx = bx - CV_BLOCKS - WT_BLOCKS;
        float* wcol = sh;
        for (int i = threadIdx.x; i < 1024; i += 256) wcol[i] = Wb[(size_t)i * 1025 + 1024];
        __syncthreads();
        int wid = threadIdx.x >> 5, lane = threadIdx.x & 31;
        float wbias = Wb[(size_t)1024 * 1025 + 1024];
        #pragma unroll
        for (int rr = 0; rr < 4; rr++) {
            int row = idx * 32 + wid * 4 + rr;
            const float* ar = reprs + (size_t)row * 1024;
            float s = 0.f;
            for (int j = lane * 4; j < 1024; j += 128) {
                float4 a = *reinterpret_cast<const float4*>(ar + j);
                s += a.x * wcol[j] + a.y * wcol[j + 1] + a.z * wcol[j + 2] + a.w * wcol[j + 3];
            }
            #pragma unroll
            for (int o = 16; o; o >>= 1) s += __shfl_xor_sync(0xffffffff, s, o);
            if (lane == 0) g_Tbias[row] = s + wbias;
        }
    } else {
        int g = (bx - CV_BLOCKS - WT_BLOCKS - 64) * 256 + threadIdx.x;
        g_keys[g] = (gold[3 * g] << 16) | (gold[3 * g + 1] << 8) | gold[3 * g + 2];
    }
}

// ===================== HMMA NT mainloop: S-stage, swizzled 64B rows =====================
// SMEM tile: R rows x 32 bf16 (64 B). Element (r,k): seg=k>>3 stored at
// seg' = seg ^ ((r>>1)&3). S stages; depth-(S-1) prefetch; uniform commit/wait.
template<int BM, int BN, int MI, int NI, int S>
__device__ __forceinline__ void mma_nt_loop(
    const __nv_bfloat16* __restrict__ Ag, int lda, int m0,
    const __nv_bfloat16* __restrict__ Bg, int ldb, int n0,
    int kbeg, int kend, float acc[MI][NI][4],
    __nv_bfloat16* As, __nv_bfloat16* Bs)   // [S][BM*32], [S][BN*32]
{
    constexpr int WC = BN / (8 * NI);
    int tid = threadIdx.x;
    int lane = tid & 31, warp = tid >> 5;
    int wm = warp / WC, wn = warp % WC;

    int ldr = tid >> 2, seg = tid & 3;
    int sw = seg ^ ((ldr >> 1) & 3);
    const __nv_bfloat16* Arow = Ag + (size_t)(m0 + ldr) * lda + seg * 8;
    const __nv_bfloat16* Brow = Bg + (size_t)(n0 + ldr) * ldb + seg * 8;
    uint32_t sa_st = sm_u32(As) + ldr * 64 + sw * 16;
    uint32_t sb_st = sm_u32(Bs) + ldr * 64 + sw * 16;
    constexpr int AIT = BM / 64, BIT = BN / 64;
    constexpr uint32_t stA = (uint32_t)BM * 64;   // bytes per stage
    constexpr uint32_t stB = (uint32_t)BN * 64;

    int a_r = lane & 15;
    uint32_t a_base = sm_u32(As) + (uint32_t)(wm * MI * 16 + a_r) * 64;
    int xa = (a_r >> 1) & 3;
    int a_hi = lane >> 4;
    int b_r = (lane & 7) + 8 * (lane >> 4);
    uint32_t b_base = sm_u32(Bs) + (uint32_t)(wn * NI * 8 + b_r) * 64;
    int xb = (b_r >> 1) & 3;
    int b_hi = (lane >> 3) & 1;

    int nc = (kend - kbeg) >> 5;
    #pragma unroll
    for (int p = 0; p < S; p++) {
        if (p < nc) {
            int kc = kbeg + p * 32;
            #pragma unroll
            for (int it = 0; it < AIT; it++)
                cp16(sa_st + p * stA + it * 4096, Arow + (size_t)it * 64 * lda + kc);
            #pragma unroll
            for (int it = 0; it < BIT; it++)
                cp16(sb_st + p * stB + it * 4096, Brow + (size_t)it * 64 * ldb + kc);
        }
        CP_COMMIT();
    }

    for (int c = 0; c < nc; c++) {
        asm volatile("cp.async.wait_group %0;\n" :: "n"(S - 1) : "memory");
        __syncthreads();
        int st = c % S;
        uint32_t a0 = a_base + st * stA;
        uint32_t b0 = b_base + st * stB;
        #pragma unroll
        for (int kk = 0; kk < 2; kk++) {
            uint32_t af[MI][4], bfr[NI][2];
            #pragma unroll
            for (int mi = 0; mi < MI; mi++)
                ldsm_x4(af[mi], a0 + mi * 1024 + ((((kk * 2 + a_hi)) ^ xa) << 4));
            #pragma unroll
            for (int nj = 0; nj < NI / 2; nj++) {
                uint32_t br[4];
                ldsm_x4(br, b0 + nj * 1024 + ((((kk * 2 + b_hi)) ^ xb) << 4));
                bfr[2 * nj][0] = br[0]; bfr[2 * nj][1] = br[1];
                bfr[2 * nj + 1][0] = br[2]; bfr[2 * nj + 1][1] = br[3];
            }
            #pragma unroll
            for (int mi = 0; mi < MI; mi++)
                #pragma unroll
                for (int ni = 0; ni < NI; ni++)
                    mma16816(acc[mi][ni], af[mi][0], af[mi][1], af[mi][2], af[mi][3],
                             bfr[ni][0], bfr[ni][1]);
        }
        __syncthreads();
        if (c + S < nc) {
            int kc = kbeg + (c + S) * 32;
            #pragma unroll
            for (int it = 0; it < AIT; it++)
                cp16(sa_st + st * stA + it * 4096, Arow + (size_t)it * 64 * lda + kc);
            #pragma unroll
            for (int it = 0; it < BIT; it++)
                cp16(sb_st + st * stB + it * 4096, Brow + (size_t)it * 64 * ldb + kc);
        }
        CP_COMMIT();
    }
}

#define NSTG 5
#define DYN_SMEM_128 (NSTG * (128 + 128) * 32 * 2)   // 80 KB

// ---- GEMM1: T_bf16 = reprs_b @ Wt^T (+ bias row), M=2048, N=1024, K=1024 ----
__global__ __launch_bounds__(256) void k_gemm1_mma(const float* __restrict__ Wb) {
    extern __shared__ __align__(16) __nv_bfloat16 dyn[];
    __nv_bfloat16* As = dyn;
    __nv_bfloat16* Bs = dyn + NSTG * 128 * 32;
    float acc[4][4][4] = {};
    int m0 = blockIdx.y * 128, n0 = blockIdx.x * 128;
    mma_nt_loop<128, 128, 4, 4, NSTG>(g_reprs_b, 1024, m0, g_Wt, 1024, n0, 0, 1024, acc, As, Bs);
    int lane = threadIdx.x & 31, warp = threadIdx.x >> 5;
    int wm = warp >> 2, wn = warp & 3, g = lane >> 2, tg = lane & 3;
    const float* brow = Wb + (size_t)1024 * 1025;
    #pragma unroll
    for (int mi = 0; mi < 4; mi++) {
        int m = m0 + wm * 64 + mi * 16 + g;
        #pragma unroll
        for (int ni = 0; ni < 4; ni++) {
            int n = n0 + wn * 32 + ni * 8 + 2 * tg;
            float b0 = brow[n], b1 = brow[n + 1];
            *reinterpret_cast<uint32_t*>(g_Tb + (size_t)m * 1024 + n) =
                pk2(acc[mi][ni][0] + b0, acc[mi][ni][1] + b1);
            *reinterpret_cast<uint32_t*>(g_Tb + (size_t)(m + 8) * 1024 + n) =
                pk2(acc[mi][ni][2] + b0, acc[mi][ni][3] + b1);
        }
    }
}

// ---- span GEMM 64x64 tiles + fused masked softplus epilogue ----
__constant__ int c_xt[10] = {0, 0, 0, 0, 1, 1, 1, 2, 2, 3};
__constant__ int c_yt[10] = {0, 1, 2, 3, 1, 2, 3, 2, 3, 3};
__global__ __launch_bounds__(256) void k_span_mma(const int* __restrict__ seq_len) {
    __shared__ __align__(16) __nv_bfloat16 As[NSTG * 64 * 32];
    __shared__ __align__(16) __nv_bfloat16 Bs[NSTG * 64 * 32];
    __shared__ float red[256];
    int t = blockIdx.x, b = blockIdx.y;
    int x0 = c_xt[t] * 64, y0 = c_yt[t] * 64;
    int slot = b * 10 + t;
    int sl = seq_len[b];
    int tid = threadIdx.x;
    if (y0 > sl) {
        if (tid == 0) { g_span_sum[slot] = 0.f; g_span_cnt2[slot] = 0.f; }
        return;
    }
    float acc[2][2][4] = {};
    mma_nt_loop<64, 64, 2, 2, NSTG>(g_Tb + (size_t)b * Ln * Dn, 1024, x0,
                                    g_reprs_b + (size_t)b * Ln * Dn, 1024, y0, 0, 1024, acc, As, Bs);
    int lane = tid & 31, warp = tid >> 5;
    int wm = warp >> 2, wn = warp & 3, g = lane >> 2, tg = lane & 3;
    float lsum = 0.f, lcnt = 0.f;
    #pragma unroll
    for (int mi = 0; mi < 2; mi++) {
        int xA = x0 + wm * 32 + mi * 16 + g;
        int xB = xA + 8;
        float tbA = g_Tbias[b * Ln + xA];
        float tbB = g_Tbias[b * Ln + xB];
        #pragma unroll
        for (int ni = 0; ni < 2; ni++) {
            int y = y0 + wn * 16 + ni * 8 + 2 * tg;
            #pragma unroll
            for (int e = 0; e < 4; e++) {
                int yy = y + (e & 1);
                int xx = (e < 2) ? xA : xB;
                float tb = (e < 2) ? tbA : tbB;
                if (yy > xx && yy <= sl) {
                    float s = acc[mi][ni][e] + tb;
                    lsum += fmaxf(s, 0.f) + log1pf(expf(-fabsf(s)));
                    lcnt += 1.f;
                }
            }
        }
    }
    red[tid] = lsum; __syncthreads();
    for (int s = 128; s > 0; s >>= 1) { if (tid < s) red[tid] += red[tid + s]; __syncthreads(); }
    float tot = red[0]; __syncthreads();
    red[tid] = lcnt; __syncthreads();
    for (int s = 128; s > 0; s >>= 1) { if (tid < s) red[tid] += red[tid + s]; __syncthreads(); }
    if (tid == 0) { g_span_sum[slot] = tot; g_span_cnt2[slot] = red[0]; }
}

// ---- h1 split-K=8: partials[ks] = gold_b @ Wp1_b^T over K slice ----
__global__ __launch_bounds__(256) void k_h1_mma() {
    extern __shared__ __align__(16) __nv_bfloat16 dyn[];
    __nv_bfloat16* As = dyn;
    __nv_bfloat16* Bs = dyn + NSTG * 128 * 32;
    float acc[4][4][4] = {};
    int n0 = blockIdx.x * 128, m0 = blockIdx.y * 128, ks = blockIdx.z;
    mma_nt_loop<128, 128, 4, 4, NSTG>(g_goldb, 2048, m0, g_Wp1b, 2048, n0,
                                      ks * 256, ks * 256 + 256, acc, As, Bs);
    int lane = threadIdx.x & 31, warp = threadIdx.x >> 5;
    int wm = warp >> 2, wn = warp & 3, g = lane >> 2, tg = lane & 3;
    float* dst = g_h1p + (size_t)ks * 512 * 256;
    #pragma unroll
    for (int mi = 0; mi < 4; mi++) {
        int m = m0 + wm * 64 + mi * 16 + g;
        #pragma unroll
        for (int ni = 0; ni < 4; ni++) {
            int n = n0 + wn * 32 + ni * 8 + 2 * tg;
            *reinterpret_cast<float2*>(dst + (size_t)m * 256 + n) =
                make_float2(acc[mi][ni][0], acc[mi][ni][1]);
            *reinterpret_cast<float2*>(dst + (size_t)(m + 8) * 256 + n) =
                make_float2(acc[mi][ni][2], acc[mi][ni][3]);
        }
    }
}

// ===================== non-tensor kernels =====================

// gold spans: warp per span, SMEM key-table dedup, -s[gold] (bf16 dot)
__global__ __launch_bounds__(256) void k_gold(const int* __restrict__ gold,
                                              const int* __restrict__ seq_len) {
    __shared__ int keys[Gn];
    __shared__ float wsum[8];
    int tid = threadIdx.x;
    for (int i = tid; i < Gn; i += 256) keys[i] = g_keys[i];
    __syncthreads();
    int wid = tid >> 5, lane = tid & 31;
    int g = blockIdx.x * 8 + wid;
    float val = 0.f;
    int key = keys[g];
    int gb = key >> 16, gl = (key >> 8) & 255, gr = key & 255;
    if (gr > gl && gr <= seq_len[gb]) {
        bool dup = false;
        for (int p = lane; p < g; p += 32)
            if (keys[p] == key) dup = true;
        dup = __any_sync(0xffffffff, dup);
        if (!dup) {
            const __nv_bfloat16* tr = g_Tb + (size_t)(gb * Ln + gl) * Dn;
            const __nv_bfloat16* rr = g_reprs_b + (size_t)(gb * Ln + gr) * Dn;
            float s = 0.f;
            for (int j = lane * 8; j < 1024; j += 256) {
                uint4 tv = *reinterpret_cast<const uint4*>(tr + j);
                uint4 rv = *reinterpret_cast<const uint4*>(rr + j);
                float2 t0 = upk2(tv.x), t1 = upk2(tv.y), t2 = upk2(tv.z), t3 = upk2(tv.w);
                float2 r0 = upk2(rv.x), r1 = upk2(rv.y), r2 = upk2(rv.z), r3 = upk2(rv.w);
                s += t0.x * r0.x + t0.y * r0.y + t1.x * r1.x + t1.y * r1.y
                   + t2.x * r2.x + t2.y * r2.y + t3.x * r3.x + t3.y * r3.y;
            }
            #pragma unroll
            for (int o = 16; o; o >>= 1) s += __shfl_xor_sync(0xffffffff, s, o);
            if (lane == 0) val = -(s + g_Tbias[gb * Ln + gl]);
        }
    }
    if (lane == 0) wsum[wid] = val;
    __syncthreads();
    if (tid == 0) {
        float t = 0.f;
        #pragma unroll
        for (int i = 0; i < 8; i++) t += wsum[i];
        g_gold_part[blockIdx.x] = t;
    }
}

// gold_repr (bf16) = concat(end-start, maxpool word_repr[start:end))
__global__ __launch_bounds__(256) void k_gold_repr(const float* __restrict__ reprs,
                                                   const int* __restrict__ span_start,
                                                   const int* __restrict__ span_end) {
    int row = blockIdx.x, tid = threadIdx.x;
    int b = row >> 6;
    int s = span_start[row], e = span_end[row];
    const float4* rs = reinterpret_cast<const float4*>(reprs + ((size_t)b * Ln + s) * Dn);
    const float4* re = reinterpret_cast<const float4*>(reprs + ((size_t)b * Ln + e) * Dn);
    float4 a = re[tid], c = rs[tid];
    uint2 o;
    o.x = pk2(a.x - c.x, a.y - c.y);
    o.y = pk2(a.z - c.z, a.w - c.w);
    *reinterpret_cast<uint2*>(g_goldb + (size_t)row * 2048 + tid * 4) = o;

    // maxpool with 4 independent accumulators (MLP) over strided words
    float m0 = NEGV, m1 = NEGV, m2 = NEGV, m3 = NEGV;
    float n0 = NEGV, n1 = NEGV, n2 = NEGV, n3 = NEGV;
    const __nv_bfloat16* wb = g_word_b + (size_t)b * Wn * Dn + tid * 4;
    int ee = min(e, Wn);
    int w = s;
    for (; w + 1 < ee; w += 2) {
        uint2 v0 = *reinterpret_cast<const uint2*>(wb + (size_t)w * Dn);
        uint2 v1 = *reinterpret_cast<const uint2*>(wb + (size_t)(w + 1) * Dn);
        float2 a0 = upk2(v0.x), a1 = upk2(v0.y);
        float2 b0 = upk2(v1.x), b1 = upk2(v1.y);
        m0 = fmaxf(m0, a0.x); m1 = fmaxf(m1, a0.y);
        m2 = fmaxf(m2, a1.x); m3 = fmaxf(m3, a1.y);
        n0 = fmaxf(n0, b0.x); n1 = fmaxf(n1, b0.y);
        n2 = fmaxf(n2, b1.x); n3 = fmaxf(n3, b1.y);
    }
    if (w < ee) {
        uint2 v0 = *reinterpret_cast<const uint2*>(wb + (size_t)w * Dn);
        float2 a0 = upk2(v0.x), a1 = upk2(v0.y);
        m0 = fmaxf(m0, a0.x); m1 = fmaxf(m1, a0.y);
        m2 = fmaxf(m2, a1.x); m3 = fmaxf(m3, a1.y);
    }
    m0 = fmaxf(m0, n0); m1 = fmaxf(m1, n1); m2 = fmaxf(m2, n2); m3 = fmaxf(m3, n3);
    uint2 p; p.x = pk2(m0, m1); p.y = pk2(m2, m3);
    *reinterpret_cast<uint2*>(g_goldb + (size_t)row * 2048 + 1024 + tid * 4) = p;
}

// fused tail: LN(relu) + h2 = h@Wp2^T+b2 + logits = h2@Lab^T + log-softmax CE
__global__ __launch_bounds__(256) void k_tail(const float* __restrict__ bp1,
                                              const float* __restrict__ gamma,
                                              const float* __restrict__ beta,
                                              const float* __restrict__ Wp2,
                                              const float* __restrict__ bp2,
                                              const float* __restrict__ lab,
                                              const int* __restrict__ chart,
                                              const int* __restrict__ action_len) {
    __shared__ float h[8][256];
    __shared__ float h2[8][256];
    __shared__ float lg[8][128];
    __shared__ float red[128];
    int tid = threadIdx.x;
    int r0 = blockIdx.x * 8;
    int warp = tid >> 5, lane = tid & 31;

    // --- LN: warp r handles row r0+r, lane covers 8 cols ---
    {
        int row = r0 + warp;
        int c0 = lane * 8;
        float x[8];
        #pragma unroll
        for (int j = 0; j < 8; j++) x[j] = bp1[c0 + j];
        #pragma unroll
        for (int p = 0; p < 8; p++) {
            const float* src = g_h1p + ((size_t)p * 512 + row) * 256 + c0;
            float4 v0 = *reinterpret_cast<const float4*>(src);
            float4 v1 = *reinterpret_cast<const float4*>(src + 4);
            x[0] += v0.x; x[1] += v0.y; x[2] += v0.z; x[3] += v0.w;
            x[4] += v1.x; x[5] += v1.y; x[6] += v1.z; x[7] += v1.w;
        }
        float sum = 0.f;
        #pragma unroll
        for (int j = 0; j < 8; j++) sum += x[j];
        #pragma unroll
        for (int o = 16; o; o >>= 1) sum += __shfl_xor_sync(0xffffffff, sum, o);
        float mean = sum * (1.0f / En);
        float s2 = 0.f;
        #pragma unroll
        for (int j = 0; j < 8; j++) { x[j] -= mean; s2 += x[j] * x[j]; }
        #pragma unroll
        for (int o = 16; o; o >>= 1) s2 += __shfl_xor_sync(0xffffffff, s2, o);
        float inv = rsqrtf(s2 * (1.0f / En) + 1e-5f);
        #pragma unroll
        for (int j = 0; j < 8; j++) {
            float y = x[j] * inv * gamma[c0 + j] + beta[c0 + j];
            h[warp][c0 + j] = fmaxf(y, 0.f);
        }
    }
    __syncthreads();
    {
        float acc[8] = {0, 0, 0, 0, 0, 0, 0, 0};
        const float4* wr = reinterpret_cast<const float4*>(Wp2 + (size_t)tid * 256);
        for (int k = 0; k < 64; k++) {
            float4 w = wr[k];
            #pragma unroll
            for (int r = 0; r < 8; r++)
                acc[r] += w.x * h[r][4 * k] + w.y * h[r][4 * k + 1]
                        + w.z * h[r][4 * k + 2] + w.w * h[r][4 * k + 3];
        }
        float bb = bp2[tid];
        #pragma unroll
        for (int r = 0; r < 8; r++) h2[r][tid] = acc[r] + bb;
    }
    __syncthreads();
    if (tid < 128) {
        float acc[8] = {0, 0, 0, 0, 0, 0, 0, 0};
        const float4* lr = reinterpret_cast<const float4*>(lab + (size_t)tid * 256);
        for (int k = 0; k < 64; k++) {
            float4 w = lr[k];
            #pragma unroll
            for (int r = 0; r < 8; r++)
                acc[r] += w.x * h2[r][4 * k] + w.y * h2[r][4 * k + 1]
                        + w.z * h2[r][4 * k + 2] + w.w * h2[r][4 * k + 3];
        }
        #pragma unroll
        for (int r = 0; r < 8; r++) lg[r][tid] = acc[r];
    }
    __syncthreads();
    for (int r = 0; r < 8; r++) {
        if (tid < 128) red[tid] = lg[r][tid];
        __syncthreads();
        for (int s = 64; s > 0; s >>= 1) { if (tid < s) red[tid] = fmaxf(red[tid], red[tid + s]); __syncthreads(); }
        float mx = red[0]; __syncthreads();
        if (tid < 128) red[tid] = expf(lg[r][tid] - mx);
        __syncthreads();
        for (int s = 64; s > 0; s >>= 1) { if (tid < s) red[tid] += red[tid + s]; __syncthreads(); }
        if (tid == 0) {
            int row = r0 + r;
            int b = row >> 6, a = row & 63;
            float lse = logf(red[0]);
            float ce = -(lg[r][chart[row]] - mx - lse);
            g_ce_part[row] = (a < action_len[b]) ? ce : 0.f;
        }
        __syncthreads();
    }
}

// final deterministic reduction
__global__ __launch_bounds__(512) void k_final(const int* __restrict__ action_len,
                                               float* __restrict__ out) {
    __shared__ float red[512];
    int tid = threadIdx.x;
    float num = (tid < 80 ? g_span_sum[tid] : 0.f) + (tid < 256 ? g_gold_part[tid] : 0.f);
    red[tid] = num; __syncthreads();
    for (int s = 256; s > 0; s >>= 1) { if (tid < s) red[tid] += red[tid + s]; __syncthreads(); }
    float span_num = red[0]; __syncthreads();

    red[tid] = (tid < 80 ? g_span_cnt2[tid] : 0.f); __syncthreads();
    for (int s = 256; s > 0; s >>= 1) { if (tid < s) red[tid] += red[tid + s]; __syncthreads(); }
    float span_cnt = red[0]; __syncthreads();

    red[tid] = g_ce_part[tid]; __syncthreads();
    for (int s = 256; s > 0; s >>= 1) { if (tid < s) red[tid] += red[tid + s]; __syncthreads(); }
    float ce_sum = red[0];

    if (tid == 0) {
        int lc = 0;
        for (int b = 0; b < Bn; b++) lc += action_len[b];
        out[0] = span_num / span_cnt + ce_sum / (float)lc;
    }
}

// ===================== launch =====================
extern "C" void kernel_launch(void* const* d_in, const int* in_sizes, int n_in,
                              void* d_out, int out_size) {
    const float* reprs      = (const float*)d_in[0];
    const float* word_repr  = (const float*)d_in[1];
    const int*   seq_len    = (const int*)d_in[2];
    const int*   gold_span  = (const int*)d_in[3];
    const int*   span_start = (const int*)d_in[4];
    const int*   span_end   = (const int*)d_in[5];
    const int*   chart      = (const int*)d_in[6];
    const int*   action_len = (const int*)d_in[7];
    const float* Wb         = (const float*)d_in[8];
    const float* Wp1        = (const float*)d_in[9];
    const float* bp1        = (const float*)d_in[10];
    const float* gamma      = (const float*)d_in[11];
    const float* beta       = (const float*)d_in[12];
    const float* Wp2        = (const float*)d_in[13];
    const float* bp2        = (const float*)d_in[14];
    const float* lab        = (const float*)d_in[15];
    float* out = (float*)d_out;

    static bool attr_done = false;
    if (!attr_done) {
        cudaFuncSetAttribute(k_gemm1_mma, cudaFuncAttributeMaxDynamicSharedMemorySize, DYN_SMEM_128);
        cudaFuncSetAttribute(k_h1_mma,    cudaFuncAttributeMaxDynamicSharedMemorySize, DYN_SMEM_128);
        attr_done = true;
    }

    // merged prelude: conversions + W^T + bias column + gold keys
    k_prelude<<<CV_BLOCKS + WT_BLOCKS + 64 + 8, 256>>>(reprs, word_repr, Wp1, Wb, gold_span);

    // tensor-core (HMMA) GEMMs, 5-stage pipelines
    k_gemm1_mma<<<dim3(8, 16), 256, DYN_SMEM_128>>>(Wb);
    k_span_mma<<<dim3(10, 8), 256>>>(seq_len);
    k_gold<<<256, 256>>>(gold_span, seq_len);

    // label path
    k_gold_repr<<<Bn * An, 256>>>(reprs, span_start, span_end);
    k_h1_mma<<<dim3(2, 4, 8), 256, DYN_SMEM_128>>>();
    k_tail<<<64, 256>>>(bp1, gamma, beta, Wp2, bp2, lab, chart, action_len);

    k_final<<<1, 512>>>(action_len, out);
}

// round 10
// speedup vs baseline: 10.5015x; 1.0494x over previous
// R10: k_gold eliminated — gold spans become a 64KB bitmap (atomicOr = .set(1.0) semantics),
// subtracted inside the span-GEMM epilogue. S=5 pipelines unchanged from R9.
#include <cuda_runtime.h>
#include <cuda_bf16.h>
#include <math.h>
#include <stdint.h>

// Problem constants
#define Bn   8
#define Ln   256
#define Dn   1024
#define An   64
#define Vn   128
#define En   256
#define Gn   2048
#define Wn   255
#define NEGV (-1000.0f)

// bf16 pack/unpack
__device__ __forceinline__ uint32_t pk2(float a, float b) {
    __nv_bfloat162 h; h.x = __float2bfloat16(a); h.y = __float2bfloat16(b);
    return *reinterpret_cast<uint32_t*>(&h);
}
__device__ __forceinline__ float2 upk2(uint32_t u) {
    __nv_bfloat162 h = *reinterpret_cast<__nv_bfloat162*>(&u);
    return __bfloat1622float2(h);
}
__device__ __forceinline__ uint32_t sm_u32(const void* p) {
    uint32_t a;
    asm("{ .reg .u64 t; cvta.to.shared.u64 t, %1; cvt.u32.u64 %0, t; }" : "=r"(a) : "l"(p));
    return a;
}

// warp mma: D(16x8,f32) += A(16x16,bf16,row) * B(16x8,bf16,col)
__device__ __forceinline__ void mma16816(float d[4], uint32_t a0, uint32_t a1,
                                         uint32_t a2, uint32_t a3,
                                         uint32_t b0, uint32_t b1) {
    asm volatile(
        "mma.sync.aligned.m16n8k16.row.col.f32.bf16.bf16.f32 "
        "{%0,%1,%2,%3}, {%4,%5,%6,%7}, {%8,%9}, {%0,%1,%2,%3};\n"
        : "+f"(d[0]), "+f"(d[1]), "+f"(d[2]), "+f"(d[3])
        : "r"(a0), "r"(a1), "r"(a2), "r"(a3), "r"(b0), "r"(b1));
}
__device__ __forceinline__ void ldsm_x4(uint32_t r[4], uint32_t addr) {
    asm volatile("ldmatrix.sync.aligned.m8n8.x4.shared.b16 {%0,%1,%2,%3}, [%4];\n"
                 : "=r"(r[0]), "=r"(r[1]), "=r"(r[2]), "=r"(r[3]) : "r"(addr));
}
__device__ __forceinline__ void cp16(uint32_t s_dst, const void* g_src) {
    asm volatile("cp.async.cg.shared.global [%0], [%1], 16;\n" :: "r"(s_dst), "l"(g_src));
}
#define CP_COMMIT() asm volatile("cp.async.commit_group;\n" ::: "memory")

// ===================== device scratch =====================
__device__ __align__(16) __nv_bfloat16 g_reprs_b[Bn * Ln * Dn];   // 4 MB
__device__ __align__(16) __nv_bfloat16 g_word_b[Bn * Wn * Dn];    // ~4 MB
__device__ __align__(16) __nv_bfloat16 g_Wp1b[En * 2 * Dn];       // 1 MB
__device__ __align__(16) __nv_bfloat16 g_Wt[Dn * Dn];             // W^T bf16, 2 MB
__device__ __align__(16) __nv_bfloat16 g_Tb[Bn * Ln * Dn];        // T bf16, 4 MB
__device__ float g_Tbias[Bn * Ln];                                 // T[:,1024] fp32
__device__ __align__(16) __nv_bfloat16 g_goldb[Bn * An * 2 * Dn]; // 2 MB
__device__ float g_h1p[8 * 512 * 256];                             // h1 split-K partials
__device__ __align__(16) uint32_t g_bitmap[Bn * Ln * Ln / 32];     // gold bitmap, 64 KB
__device__ float g_span_sum[80];
__device__ float g_span_cnt2[80];
__device__ float g_ce_part[512];

// ===================== merged prelude =====================
// blocks [0,2300): fp32->bf16 conversion of reprs/word_repr/Wp1
// blocks [2300,2556): W^T bf16 64x64 transpose tiles
// blocks [2556,2620): T bias column dot products
// blocks [2620,2628): zero gold bitmap
#define N_REPRS (Bn * Ln * Dn)        // 2097152
#define N_WORD  (Bn * Wn * Dn)        // 2088960
#define N_WP1   (En * 2 * Dn)         // 524288
#define CV_BLOCKS 2300
#define WT_BLOCKS 256
__global__ __launch_bounds__(256) void k_prelude(const float* __restrict__ reprs,
                                                 const float* __restrict__ word,
                                                 const float* __restrict__ wp1,
                                                 const float* __restrict__ Wb) {
    __shared__ float sh[64 * 65];
    int bx = blockIdx.x;
    if (bx < CV_BLOCKS) {
        size_t i = ((size_t)bx * 256 + threadIdx.x) * 8;
        const float* src; __nv_bfloat16* dst;
        if (i < N_REPRS) { src = reprs + i; dst = g_reprs_b + i; }
        else if (i < (size_t)N_REPRS + N_WORD) { size_t j = i - N_REPRS; src = word + j; dst = g_word_b + j; }
        else { size_t j = i - N_REPRS - N_WORD; src = wp1 + j; dst = g_Wp1b + j; }
        float4 a = *reinterpret_cast<const float4*>(src);
        float4 b = *reinterpret_cast<const float4*>(src + 4);
        uint4 o;
        o.x = pk2(a.x, a.y); o.y = pk2(a.z, a.w);
        o.z = pk2(b.x, b.y); o.w = pk2(b.z, b.w);
        *reinterpret_cast<uint4*>(dst) = o;
    } else if (bx < CV_BLOCKS + WT_BLOCKS) {
        int idx = bx - CV_BLOCKS;
        int n0 = (idx & 15) * 64, k0 = (idx >> 4) * 64;
        int r = threadIdx.x >> 2, cq = (threadIdx.x & 3) * 16;
        #pragma unroll
        for (int i = 0; i < 16; i++)
            sh[r * 65 + cq + i] = Wb[(size_t)(k0 + r) * 1025 + n0 + cq + i];
        __syncthreads();
        uint32_t pk[8];
        #pragma unroll
        for (int j = 0; j < 8; j++)
            pk[j] = pk2(sh[(cq + 2 * j) * 65 + r], sh[(cq + 2 * j + 1) * 65 + r]);
        __nv_bfloat16* dst = g_Wt + (size_t)(n0 + r) * 1024 + k0 + cq;
        *reinterpret_cast<uint4*>(dst)     = make_uint4(pk[0], pk[1], pk[2], pk[3]);
        *reinterpret_cast<uint4*>(dst + 8) = make_uint4(pk[4], pk[5], pk[6], pk[7]);
    } else if (bx < CV_BLOCKS + WT_BLOCKS + 64) {
        int idx = bx - CV_BLOCKS - WT_BLOCKS;
        float* wcol = sh;
        for (int i = threadIdx.x; i < 1024; i += 256) wcol[i] = Wb[(size_t)i * 1025 + 1024];
        __syncthreads();
        int wid = threadIdx.x >> 5, lane = threadIdx.x & 31;
        float wbias = Wb[(size_t)1024 * 1025 + 1024];
        #pragma unroll
        for (int rr = 0; rr < 4; rr++) {
            int row = idx * 32 + wid * 4 + rr;
            const float* ar = reprs + (size_t)row * 1024;
            float s = 0.f;
            for (int j = lane * 4; j < 1024; j += 128) {
                float4 a = *reinterpret_cast<const float4*>(ar + j);
                s += a.x * wcol[j] + a.y * wcol[j + 1] + a.z * wcol[j + 2] + a.w * wcol[j + 3];
            }
            #pragma unroll
            for (int o = 16; o; o >>= 1) s += __shfl_xor_sync(0xffffffff, s, o);
            if (lane == 0) g_Tbias[row] = s + wbias;
        }
    } else {
        // zero gold bitmap: 16384 words / 8 blocks = 2048 words/block = 8 KB
        int idx = (bx - CV_BLOCKS - WT_BLOCKS - 64) * 512 + threadIdx.x * 2;
        *reinterpret_cast<uint2*>(g_bitmap + idx) = make_uint2(0u, 0u);
    }
}

// set gold bits: atomicOr is idempotent == reference's .set(1.0)
__global__ __launch_bounds__(256) void k_setbits(const int* __restrict__ gold) {
    int g = blockIdx.x * 256 + threadIdx.x;
    int gb = gold[3 * g], gl = gold[3 * g + 1], gr = gold[3 * g + 2];
    int idx = (gb << 16) | (gl << 8) | gr;
    atomicOr(&g_bitmap[idx >> 5], 1u << (idx & 31));
}

// ===================== HMMA NT mainloop: S-stage, swizzled 64B rows =====================
template<int BM, int BN, int MI, int NI, int S>
__device__ __forceinline__ void mma_nt_loop(
    const __nv_bfloat16* __restrict__ Ag, int lda, int m0,
    const __nv_bfloat16* __restrict__ Bg, int ldb, int n0,
    int kbeg, int kend, float acc[MI][NI][4],
    __nv_bfloat16* As, __nv_bfloat16* Bs)   // [S][BM*32], [S][BN*32]
{
    constexpr int WC = BN / (8 * NI);
    int tid = threadIdx.x;
    int lane = tid & 31, warp = tid >> 5;
    int wm = warp / WC, wn = warp % WC;

    int ldr = tid >> 2, seg = tid & 3;
    int sw = seg ^ ((ldr >> 1) & 3);
    const __nv_bfloat16* Arow = Ag + (size_t)(m0 + ldr) * lda + seg * 8;
    const __nv_bfloat16* Brow = Bg + (size_t)(n0 + ldr) * ldb + seg * 8;
    uint32_t sa_st = sm_u32(As) + ldr * 64 + sw * 16;
    uint32_t sb_st = sm_u32(Bs) + ldr * 64 + sw * 16;
    constexpr int AIT = BM / 64, BIT = BN / 64;
    constexpr uint32_t stA = (uint32_t)BM * 64;
    constexpr uint32_t stB = (uint32_t)BN * 64;

    int a_r = lane & 15;
    uint32_t a_base = sm_u32(As) + (uint32_t)(wm * MI * 16 + a_r) * 64;
    int xa = (a_r >> 1) & 3;
    int a_hi = lane >> 4;
    int b_r = (lane & 7) + 8 * (lane >> 4);
    uint32_t b_base = sm_u32(Bs) + (uint32_t)(wn * NI * 8 + b_r) * 64;
    int xb = (b_r >> 1) & 3;
    int b_hi = (lane >> 3) & 1;

    int nc = (kend - kbeg) >> 5;
    #pragma unroll
    for (int p = 0; p < S; p++) {
        if (p < nc) {
            int kc = kbeg + p * 32;
            #pragma unroll
            for (int it = 0; it < AIT; it++)
                cp16(sa_st + p * stA + it * 4096, Arow + (size_t)it * 64 * lda + kc);
            #pragma unroll
            for (int it = 0; it < BIT; it++)
                cp16(sb_st + p * stB + it * 4096, Brow + (size_t)it * 64 * ldb + kc);
        }
        CP_COMMIT();
    }

    for (int c = 0; c < nc; c++) {
        asm volatile("cp.async.wait_group %0;\n" :: "n"(S - 1) : "memory");
        __syncthreads();
        int st = c % S;
        uint32_t a0 = a_base + st * stA;
        uint32_t b0 = b_base + st * stB;
        #pragma unroll
        for (int kk = 0; kk < 2; kk++) {
            uint32_t af[MI][4], bfr[NI][2];
            #pragma unroll
            for (int mi = 0; mi < MI; mi++)
                ldsm_x4(af[mi], a0 + mi * 1024 + ((((kk * 2 + a_hi)) ^ xa) << 4));
            #pragma unroll
            for (int nj = 0; nj < NI / 2; nj++) {
                uint32_t br[4];
                ldsm_x4(br, b0 + nj * 1024 + ((((kk * 2 + b_hi)) ^ xb) << 4));
                bfr[2 * nj][0] = br[0]; bfr[2 * nj][1] = br[1];
                bfr[2 * nj + 1][0] = br[2]; bfr[2 * nj + 1][1] = br[3];
            }
            #pragma unroll
            for (int mi = 0; mi < MI; mi++)
                #pragma unroll
                for (int ni = 0; ni < NI; ni++)
                    mma16816(acc[mi][ni], af[mi][0], af[mi][1], af[mi][2], af[mi][3],
                             bfr[ni][0], bfr[ni][1]);
        }
        __syncthreads();
        if (c + S < nc) {
            int kc = kbeg + (c + S) * 32;
            #pragma unroll
            for (int it = 0; it < AIT; it++)
                cp16(sa_st + st * stA + it * 4096, Arow + (size_t)it * 64 * lda + kc);
            #pragma unroll
            for (int it = 0; it < BIT; it++)
                cp16(sb_st + st * stB + it * 4096, Brow + (size_t)it * 64 * ldb + kc);
        }
        CP_COMMIT();
    }
}

#define NSTG 5
#define DYN_SMEM_128 (NSTG * (128 + 128) * 32 * 2)   // 80 KB

// ---- GEMM1: T_bf16 = reprs_b @ Wt^T (+ bias row), M=2048, N=1024, K=1024 ----
__global__ __launch_bounds__(256) void k_gemm1_mma(const float* __restrict__ Wb) {
    extern __shared__ __align__(16) __nv_bfloat16 dyn[];
    __nv_bfloat16* As = dyn;
    __nv_bfloat16* Bs = dyn + NSTG * 128 * 32;
    float acc[4][4][4] = {};
    int m0 = blockIdx.y * 128, n0 = blockIdx.x * 128;
    mma_nt_loop<128, 128, 4, 4, NSTG>(g_reprs_b, 1024, m0, g_Wt, 1024, n0, 0, 1024, acc, As, Bs);
    int lane = threadIdx.x & 31, warp = threadIdx.x >> 5;
    int wm = warp >> 2, wn = warp & 3, g = lane >> 2, tg = lane & 3;
    const float* brow = Wb + (size_t)1024 * 1025;
    #pragma unroll
    for (int mi = 0; mi < 4; mi++) {
        int m = m0 + wm * 64 + mi * 16 + g;
        #pragma unroll
        for (int ni = 0; ni < 4; ni++) {
            int n = n0 + wn * 32 + ni * 8 + 2 * tg;
            float b0 = brow[n], b1 = brow[n + 1];
            *reinterpret_cast<uint32_t*>(g_Tb + (size_t)m * 1024 + n) =
                pk2(acc[mi][ni][0] + b0, acc[mi][ni][1] + b1);
            *reinterpret_cast<uint32_t*>(g_Tb + (size_t)(m + 8) * 1024 + n) =
                pk2(acc[mi][ni][2] + b0, acc[mi][ni][3] + b1);
        }
    }
}

// ---- span GEMM 64x64 tiles + fused masked BCE epilogue (softplus - s*gold) ----
__constant__ int c_xt[10] = {0, 0, 0, 0, 1, 1, 1, 2, 2, 3};
__constant__ int c_yt[10] = {0, 1, 2, 3, 1, 2, 3, 2, 3, 3};
__global__ __launch_bounds__(256) void k_span_mma(const int* __restrict__ seq_len) {
    __shared__ __align__(16) __nv_bfloat16 As[NSTG * 64 * 32];
    __shared__ __align__(16) __nv_bfloat16 Bs[NSTG * 64 * 32];
    __shared__ float red[256];
    int t = blockIdx.x, b = blockIdx.y;
    int x0 = c_xt[t] * 64, y0 = c_yt[t] * 64;
    int slot = b * 10 + t;
    int sl = seq_len[b];
    int tid = threadIdx.x;
    if (y0 > sl) {
        if (tid == 0) { g_span_sum[slot] = 0.f; g_span_cnt2[slot] = 0.f; }
        return;
    }
    float acc[2][2][4] = {};
    mma_nt_loop<64, 64, 2, 2, NSTG>(g_Tb + (size_t)b * Ln * Dn, 1024, x0,
                                    g_reprs_b + (size_t)b * Ln * Dn, 1024, y0, 0, 1024, acc, As, Bs);
    int lane = tid & 31, warp = tid >> 5;
    int wm = warp >> 2, wn = warp & 3, g = lane >> 2, tg = lane & 3;
    float lsum = 0.f, lcnt = 0.f;
    #pragma unroll
    for (int mi = 0; mi < 2; mi++) {
        int xA = x0 + wm * 32 + mi * 16 + g;
        int xB = xA + 8;
        float tbA = g_Tbias[b * Ln + xA];
        float tbB = g_Tbias[b * Ln + xB];
        #pragma unroll
        for (int ni = 0; ni < 2; ni++) {
            int y = y0 + wn * 16 + ni * 8 + 2 * tg;
            #pragma unroll
            for (int e = 0; e < 4; e++) {
                int yy = y + (e & 1);
                int xx = (e < 2) ? xA : xB;
                float tb = (e < 2) ? tbA : tbB;
                if (yy > xx && yy <= sl) {
                    float s = acc[mi][ni][e] + tb;
                    lsum += fmaxf(s, 0.f) + log1pf(expf(-fabsf(s)));
                    int idx = (b << 16) | (xx << 8) | yy;
                    if ((g_bitmap[idx >> 5] >> (idx & 31)) & 1u) lsum -= s;
                    lcnt += 1.f;
                }
            }
        }
    }
    red[tid] = lsum; __syncthreads();
    for (int s = 128; s > 0; s >>= 1) { if (tid < s) red[tid] += red[tid + s]; __syncthreads(); }
    float tot = red[0]; __syncthreads();
    red[tid] = lcnt; __syncthreads();
    for (int s = 128; s > 0; s >>= 1) { if (tid < s) red[tid] += red[tid + s]; __syncthreads(); }
    if (tid == 0) { g_span_sum[slot] = tot; g_span_cnt2[slot] = red[0]; }
}

// ---- h1 split-K=8: partials[ks] = gold_b @ Wp1_b^T over K slice ----
__global__ __launch_bounds__(256) void k_h1_mma() {
    extern __shared__ __align__(16) __nv_bfloat16 dyn[];
    __nv_bfloat16* As = dyn;
    __nv_bfloat16* Bs = dyn + NSTG * 128 * 32;
    float acc[4][4][4] = {};
    int n0 = blockIdx.x * 128, m0 = blockIdx.y * 128, ks = blockIdx.z;
    mma_nt_loop<128, 128, 4, 4, NSTG>(g_goldb, 2048, m0, g_Wp1b, 2048, n0,
                                      ks * 256, ks * 256 + 256, acc, As, Bs);
    int lane = threadIdx.x & 31, warp = threadIdx.x >> 5;
    int wm = warp >> 2, wn = warp & 3, g = lane >> 2, tg = lane & 3;
    float* dst = g_h1p + (size_t)ks * 512 * 256;
    #pragma unroll
    for (int mi = 0; mi < 4; mi++) {
        int m = m0 + wm * 64 + mi * 16 + g;
        #pragma unroll
        for (int ni = 0; ni < 4; ni++) {
            int n = n0 + wn * 32 + ni * 8 + 2 * tg;
            *reinterpret_cast<float2*>(dst + (size_t)m * 256 + n) =
                make_float2(acc[mi][ni][0], acc[mi][ni][1]);
            *reinterpret_cast<float2*>(dst + (size_t)(m + 8) * 256 + n) =
                make_float2(acc[mi][ni][2], acc[mi][ni][3]);
        }
    }
}

// ===================== non-tensor kernels =====================

// gold_repr (bf16) = concat(end-start, maxpool word_repr[start:end))
__global__ __launch_bounds__(256) void k_gold_repr(const float* __restrict__ reprs,
                                                   const int* __restrict__ span_start,
                                                   const int* __restrict__ span_end) {
    int row = blockIdx.x, tid = threadIdx.x;
    int b = row >> 6;
    int s = span_start[row], e = span_end[row];
    const float4* rs = reinterpret_cast<const float4*>(reprs + ((size_t)b * Ln + s) * Dn);
    const float4* re = reinterpret_cast<const float4*>(reprs + ((size_t)b * Ln + e) * Dn);
    float4 a = re[tid], c = rs[tid];
    uint2 o;
    o.x = pk2(a.x - c.x, a.y - c.y);
    o.y = pk2(a.z - c.z, a.w - c.w);
    *reinterpret_cast<uint2*>(g_goldb + (size_t)row * 2048 + tid * 4) = o;

    float m0 = NEGV, m1 = NEGV, m2 = NEGV, m3 = NEGV;
    float n0 = NEGV, n1 = NEGV, n2 = NEGV, n3 = NEGV;
    const __nv_bfloat16* wb = g_word_b + (size_t)b * Wn * Dn + tid * 4;
    int ee = min(e, Wn);
    int w = s;
    for (; w + 1 < ee; w += 2) {
        uint2 v0 = *reinterpret_cast<const uint2*>(wb + (size_t)w * Dn);
        uint2 v1 = *reinterpret_cast<const uint2*>(wb + (size_t)(w + 1) * Dn);
        float2 a0 = upk2(v0.x), a1 = upk2(v0.y);
        float2 b0 = upk2(v1.x), b1 = upk2(v1.y);
        m0 = fmaxf(m0, a0.x); m1 = fmaxf(m1, a0.y);
        m2 = fmaxf(m2, a1.x); m3 = fmaxf(m3, a1.y);
        n0 = fmaxf(n0, b0.x); n1 = fmaxf(n1, b0.y);
        n2 = fmaxf(n2, b1.x); n3 = fmaxf(n3, b1.y);
    }
    if (w < ee) {
        uint2 v0 = *reinterpret_cast<const uint2*>(wb + (size_t)w * Dn);
        float2 a0 = upk2(v0.x), a1 = upk2(v0.y);
        m0 = fmaxf(m0, a0.x); m1 = fmaxf(m1, a0.y);
        m2 = fmaxf(m2, a1.x); m3 = fmaxf(m3, a1.y);
    }
    m0 = fmaxf(m0, n0); m1 = fmaxf(m1, n1); m2 = fmaxf(m2, n2); m3 = fmaxf(m3, n3);
    uint2 p; p.x = pk2(m0, m1); p.y = pk2(m2, m3);
    *reinterpret_cast<uint2*>(g_goldb + (size_t)row * 2048 + 1024 + tid * 4) = p;
}

// fused tail: LN(relu) + h2 = h@Wp2^T+b2 + logits = h2@Lab^T + log-softmax CE
__global__ __launch_bounds__(256) void k_tail(const float* __restrict__ bp1,
                                              const float* __restrict__ gamma,
                                              const float* __restrict__ beta,
                                              const float* __restrict__ Wp2,
                                              const float* __restrict__ bp2,
                                              const float* __restrict__ lab,
                                              const int* __restrict__ chart,
                                              const int* __restrict__ action_len) {
    __shared__ float h[8][256];
    __shared__ float h2[8][256];
    __shared__ float lg[8][128];
    __shared__ float red[128];
    int tid = threadIdx.x;
    int r0 = blockIdx.x * 8;
    int warp = tid >> 5, lane = tid & 31;

    {
        int row = r0 + warp;
        int c0 = lane * 8;
        float x[8];
        #pragma unroll
        for (int j = 0; j < 8; j++) x[j] = bp1[c0 + j];
        #pragma unroll
        for (int p = 0; p < 8; p++) {
            const float* src = g_h1p + ((size_t)p * 512 + row) * 256 + c0;
            float4 v0 = *reinterpret_cast<const float4*>(src);
            float4 v1 = *reinterpret_cast<const float4*>(src + 4);
            x[0] += v0.x; x[1] += v0.y; x[2] += v0.z; x[3] += v0.w;
            x[4] += v1.x; x[5] += v1.y; x[6] += v1.z; x[7] += v1.w;
        }
        float sum = 0.f;
        #pragma unroll
        for (int j = 0; j < 8; j++) sum += x[j];
        #pragma unroll
        for (int o = 16; o; o >>= 1) sum += __shfl_xor_sync(0xffffffff, sum, o);
        float mean = sum * (1.0f / En);
        float s2 = 0.f;
        #pragma unroll
        for (int j = 0; j < 8; j++) { x[j] -= mean; s2 += x[j] * x[j]; }
        #pragma unroll
        for (int o = 16; o; o >>= 1) s2 += __shfl_xor_sync(0xffffffff, s2, o);
        float inv = rsqrtf(s2 * (1.0f / En) + 1e-5f);
        #pragma unroll
        for (int j = 0; j < 8; j++) {
            float y = x[j] * inv * gamma[c0 + j] + beta[c0 + j];
            h[warp][c0 + j] = fmaxf(y, 0.f);
        }
    }
    __syncthreads();
    {
        float acc[8] = {0, 0, 0, 0, 0, 0, 0, 0};
        const float4* wr = reinterpret_cast<const float4*>(Wp2 + (size_t)tid * 256);
        for (int k = 0; k < 64; k++) {
            float4 w = wr[k];
            #pragma unroll
            for (int r = 0; r < 8; r++)
                acc[r] += w.x * h[r][4 * k] + w.y * h[r][4 * k + 1]
                        + w.z * h[r][4 * k + 2] + w.w * h[r][4 * k + 3];
        }
        float bb = bp2[tid];
        #pragma unroll
        for (int r = 0; r < 8; r++) h2[r][tid] = acc[r] + bb;
    }
    __syncthreads();
    if (tid < 128) {
        float acc[8] = {0, 0, 0, 0, 0, 0, 0, 0};
        const float4* lr = reinterpret_cast<const float4*>(lab + (size_t)tid * 256);
        for (int k = 0; k < 64; k++) {
            float4 w = lr[k];
            #pragma unroll
            for (int r = 0; r < 8; r++)
                acc[r] += w.x * h2[r][4 * k] + w.y * h2[r][4 * k + 1]
                        + w.z * h2[r][4 * k + 2] + w.w * h2[r][4 * k + 3];
        }
        #pragma unroll
        for (int r = 0; r < 8; r++) lg[r][tid] = acc[r];
    }
    __syncthreads();
    for (int r = 0; r < 8; r++) {
        if (tid < 128) red[tid] = lg[r][tid];
        __syncthreads();
        for (int s = 64; s > 0; s >>= 1) { if (tid < s) red[tid] = fmaxf(red[tid], red[tid + s]); __syncthreads(); }
        float mx = red[0]; __syncthreads();
        if (tid < 128) red[tid] = expf(lg[r][tid] - mx);
        __syncthreads();
        for (int s = 64; s > 0; s >>= 1) { if (tid < s) red[tid] += red[tid + s]; __syncthreads(); }
        if (tid == 0) {
            int row = r0 + r;
            int b = row >> 6, a = row & 63;
            float lse = logf(red[0]);
            float ce = -(lg[r][chart[row]] - mx - lse);
            g_ce_part[row] = (a < action_len[b]) ? ce : 0.f;
        }
        __syncthreads();
    }
}

// final deterministic reduction
__global__ __launch_bounds__(512) void k_final(const int* __restrict__ action_len,
                                               float* __restrict__ out) {
    __shared__ float red[512];
    int tid = threadIdx.x;
    red[tid] = (tid < 80 ? g_span_sum[tid] : 0.f); __syncthreads();
    for (int s = 256; s > 0; s >>= 1) { if (tid < s) red[tid] += red[tid + s]; __syncthreads(); }
    float span_num = red[0]; __syncthreads();

    red[tid] = (tid < 80 ? g_span_cnt2[tid] : 0.f); __syncthreads();
    for (int s = 256; s > 0; s >>= 1) { if (tid < s) red[tid] += red[tid + s]; __syncthreads(); }
    float span_cnt = red[0]; __syncthreads();

    red[tid] = g_ce_part[tid]; __syncthreads();
    for (int s = 256; s > 0; s >>= 1) { if (tid < s) red[tid] += red[tid + s]; __syncthreads(); }
    float ce_sum = red[0];

    if (tid == 0) {
        int lc = 0;
        for (int b = 0; b < Bn; b++) lc += action_len[b];
        out[0] = span_num / span_cnt + ce_sum / (float)lc;
    }
}

// ===================== launch =====================
extern "C" void kernel_launch(void* const* d_in, const int* in_sizes, int n_in,
                              void* d_out, int out_size) {
    const float* reprs      = (const float*)d_in[0];
    const float* word_repr  = (const float*)d_in[1];
    const int*   seq_len    = (const int*)d_in[2];
    const int*   gold_span  = (const int*)d_in[3];
    const int*   span_start = (const int*)d_in[4];
    const int*   span_end   = (const int*)d_in[5];
    const int*   chart      = (const int*)d_in[6];
    const int*   action_len = (const int*)d_in[7];
    const float* Wb         = (const float*)d_in[8];
    const float* Wp1        = (const float*)d_in[9];
    const float* bp1        = (const float*)d_in[10];
    const float* gamma      = (const float*)d_in[11];
    const float* beta       = (const float*)d_in[12];
    const float* Wp2        = (const float*)d_in[13];
    const float* bp2        = (const float*)d_in[14];
    const float* lab        = (const float*)d_in[15];
    float* out = (float*)d_out;

    static bool attr_done = false;
    if (!attr_done) {
        cudaFuncSetAttribute(k_gemm1_mma, cudaFuncAttributeMaxDynamicSharedMemorySize, DYN_SMEM_128);
        cudaFuncSetAttribute(k_h1_mma,    cudaFuncAttributeMaxDynamicSharedMemorySize, DYN_SMEM_128);
        attr_done = true;
    }

    // prelude: conversions + W^T + bias column + bitmap zero; then gold bits
    k_prelude<<<CV_BLOCKS + WT_BLOCKS + 64 + 8, 256>>>(reprs, word_repr, Wp1, Wb);
    k_setbits<<<8, 256>>>(gold_span);

    // tensor-core (HMMA) GEMMs, 5-stage pipelines
    k_gemm1_mma<<<dim3(8, 16), 256, DYN_SMEM_128>>>(Wb);
    k_span_mma<<<dim3(10, 8), 256>>>(seq_len);

    // label path
    k_gold_repr<<<Bn * An, 256>>>(reprs, span_start, span_end);
    k_h1_mma<<<dim3(2, 4, 8), 256, DYN_SMEM_128>>>();
    k_tail<<<64, 256>>>(bp1, gamma, beta, Wp2, bp2, lab, chart, action_len);

    k_final<<<1, 512>>>(action_len, out);
}